// round 3
// baseline (speedup 1.0000x reference)
#include <cuda_runtime.h>
#include <math.h>

// Problem constants (fixed by the reference)
constexpr int PB = 2;      // batch
constexpr int PS = 2048;   // seq len
constexpr int PD = 1024;   // model dim
constexpr int PH = 16;     // heads
constexpr int PDK = 64;    // head dim
constexpr int PM = PB * PS;       // 4096 rows for projections
constexpr int PE = PB * PS * PD;  // elements per activation tensor

// Scratch (device globals: allocation-free, graph-capturable)
__device__ float g_Q[PE];
__device__ float g_K[PE];
__device__ float g_V[PE];
__device__ float g_A[PE];

// ---------------------------------------------------------------------------
// GEMM: C[m,n] = sum_k A[m,k] * W[n,k] + bias[n]
// A: [PM, PD] row-major, W: [PD, PD] row-major (both K-contiguous).
// 128x128 block tile, BK=16, 256 threads, 8x8 per-thread micro-tile.
// ---------------------------------------------------------------------------
__global__ void __launch_bounds__(256)
gemm_abt(const float* __restrict__ A, const float* __restrict__ W,
         const float* __restrict__ bias, float* __restrict__ C)
{
    constexpr int BM = 128, BN = 128, BK = 16, LDT = BM + 4;
    __shared__ float As[BK][LDT];
    __shared__ float Ws[BK][LDT];

    const int t  = threadIdx.x;
    const int tx = t & 15;       // 0..15 -> cols tx*8
    const int ty = t >> 4;       // 0..15 -> rows ty*8
    const int bx = blockIdx.x;   // N tile
    const int by = blockIdx.y;   // M tile

    const float* Ab = A + (size_t)(by * BM) * PD;
    const float* Wb = W + (size_t)(bx * BN) * PD;

    float acc[8][8];
#pragma unroll
    for (int i = 0; i < 8; i++)
#pragma unroll
        for (int j = 0; j < 8; j++) acc[i][j] = 0.f;

    for (int k0 = 0; k0 < PD; k0 += BK) {
        // Load 128x16 tiles of A and W, transposed into smem (k-major rows).
#pragma unroll
        for (int i = 0; i < 2; i++) {
            int idx = t + i * 256;        // 0..511
            int row = idx >> 2;           // 0..127
            int kq  = (idx & 3) << 2;     // 0,4,8,12
            float4 av = *(const float4*)(Ab + (size_t)row * PD + k0 + kq);
            As[kq + 0][row] = av.x; As[kq + 1][row] = av.y;
            As[kq + 2][row] = av.z; As[kq + 3][row] = av.w;
            float4 wv = *(const float4*)(Wb + (size_t)row * PD + k0 + kq);
            Ws[kq + 0][row] = wv.x; Ws[kq + 1][row] = wv.y;
            Ws[kq + 2][row] = wv.z; Ws[kq + 3][row] = wv.w;
        }
        __syncthreads();

#pragma unroll
        for (int k = 0; k < BK; k++) {
            float a[8], b[8];
            *(float4*)&a[0] = *(const float4*)&As[k][ty * 8];
            *(float4*)&a[4] = *(const float4*)&As[k][ty * 8 + 4];
            *(float4*)&b[0] = *(const float4*)&Ws[k][tx * 8];
            *(float4*)&b[4] = *(const float4*)&Ws[k][tx * 8 + 4];
#pragma unroll
            for (int i = 0; i < 8; i++)
#pragma unroll
                for (int j = 0; j < 8; j++)
                    acc[i][j] += a[i] * b[j];
        }
        __syncthreads();
    }

    const int row0 = by * BM + ty * 8;
    const int col0 = bx * BN + tx * 8;
    float4 b0 = *(const float4*)(bias + col0);
    float4 b1 = *(const float4*)(bias + col0 + 4);
#pragma unroll
    for (int i = 0; i < 8; i++) {
        float4 v0 = make_float4(acc[i][0] + b0.x, acc[i][1] + b0.y,
                                acc[i][2] + b0.z, acc[i][3] + b0.w);
        float4 v1 = make_float4(acc[i][4] + b1.x, acc[i][5] + b1.y,
                                acc[i][6] + b1.z, acc[i][7] + b1.w);
        *(float4*)(C + (size_t)(row0 + i) * PD + col0)     = v0;
        *(float4*)(C + (size_t)(row0 + i) * PD + col0 + 4) = v1;
    }
}

// ---------------------------------------------------------------------------
// Causal flash attention, fp32.
// Block = (q-tile of 64, one (b,h)). 256 threads, 4x4 micro-tiles.
// Q/K staged transposed (dk-major) in smem, V natural, P staged for PV GEMM.
// Online softmax state (m, l) replicated across the 16 threads of a row group
// (warp-shuffle row reductions keep the replicas identical).
// ---------------------------------------------------------------------------
__global__ void __launch_bounds__(256)
attn_kernel(const float* __restrict__ Q, const float* __restrict__ Kin,
            const float* __restrict__ Vin, float* __restrict__ O)
{
    constexpr int TS  = 64;
    constexpr int LDT = 68;   // pad for conflict-free float4 lanes
    extern __shared__ float sm[];
    float* Qs = sm;                  // [dk][r]
    float* Ks = Qs + TS * LDT;       // [dk][c]
    float* Vs = Ks + TS * LDT;       // [c][dv]
    float* Ps = Vs + TS * LDT;       // [c][r]

    const int jq = blockIdx.x;       // q tile 0..31
    const int bh = blockIdx.y;       // 0..31
    const int b  = bh >> 4;
    const int h  = bh & 15;
    const int t  = threadIdx.x;
    const int tx = t & 15;           // key / dv group
    const int ty = t >> 4;           // query row group

    const float* Qb = Q   + ((size_t)b * PS + (size_t)jq * TS) * PD + h * PDK;
    const float* Kb = Kin + (size_t)b * PS * PD + h * PDK;
    const float* Vb = Vin + (size_t)b * PS * PD + h * PDK;

    // Load Q tile transposed: Qs[dk][r] = Q[r][dk]
#pragma unroll
    for (int i = 0; i < 4; i++) {
        int idx = t + i * 256;       // 0..1023
        int row = idx >> 4;          // 0..63
        int kq  = (idx & 15) << 2;   // 0..60
        float4 qv = *(const float4*)(Qb + (size_t)row * PD + kq);
        Qs[(kq + 0) * LDT + row] = qv.x; Qs[(kq + 1) * LDT + row] = qv.y;
        Qs[(kq + 2) * LDT + row] = qv.z; Qs[(kq + 3) * LDT + row] = qv.w;
    }

    float m_i[4], l_i[4], o[4][4];
#pragma unroll
    for (int i = 0; i < 4; i++) {
        m_i[i] = -1e30f;
        l_i[i] = 0.f;
#pragma unroll
        for (int j = 0; j < 4; j++) o[i][j] = 0.f;
    }

    for (int kt = 0; kt <= jq; kt++) {
        __syncthreads();  // prior PV done reading Vs/Ps before overwrite
#pragma unroll
        for (int i = 0; i < 4; i++) {
            int idx = t + i * 256;
            int row = idx >> 4;
            int kq  = (idx & 15) << 2;
            const float* kp = Kb + ((size_t)kt * TS + row) * PD + kq;
            float4 kv = *(const float4*)kp;
            Ks[(kq + 0) * LDT + row] = kv.x; Ks[(kq + 1) * LDT + row] = kv.y;
            Ks[(kq + 2) * LDT + row] = kv.z; Ks[(kq + 3) * LDT + row] = kv.w;
            const float* vp = Vb + ((size_t)kt * TS + row) * PD + kq;
            float4 vv = *(const float4*)vp;
            *(float4*)(Vs + row * LDT + kq) = vv;
        }
        __syncthreads();

        // S = Q Kᵀ (scaled later)
        float sc[4][4];
#pragma unroll
        for (int i = 0; i < 4; i++)
#pragma unroll
            for (int j = 0; j < 4; j++) sc[i][j] = 0.f;

#pragma unroll
        for (int k = 0; k < TS; k++) {
            float4 q4 = *(const float4*)(Qs + k * LDT + ty * 4);
            float4 k4 = *(const float4*)(Ks + k * LDT + tx * 4);
            float qa[4] = {q4.x, q4.y, q4.z, q4.w};
            float kb[4] = {k4.x, k4.y, k4.z, k4.w};
#pragma unroll
            for (int i = 0; i < 4; i++)
#pragma unroll
                for (int j = 0; j < 4; j++)
                    sc[i][j] += qa[i] * kb[j];
        }

        const float scale = 0.125f;   // 1/sqrt(64)
        if (kt == jq) {
#pragma unroll
            for (int i = 0; i < 4; i++)
#pragma unroll
                for (int j = 0; j < 4; j++)
                    sc[i][j] = (tx * 4 + j <= ty * 4 + i) ? sc[i][j] * scale
                                                          : -1e30f;
        } else {
#pragma unroll
            for (int i = 0; i < 4; i++)
#pragma unroll
                for (int j = 0; j < 4; j++) sc[i][j] *= scale;
        }

        // Online softmax update (row reductions across the 16-lane group)
#pragma unroll
        for (int i = 0; i < 4; i++) {
            float rmax = fmaxf(fmaxf(sc[i][0], sc[i][1]),
                               fmaxf(sc[i][2], sc[i][3]));
#pragma unroll
            for (int off = 8; off > 0; off >>= 1)
                rmax = fmaxf(rmax, __shfl_xor_sync(0xffffffffu, rmax, off));
            float mnew  = fmaxf(m_i[i], rmax);
            float alpha = __expf(m_i[i] - mnew);
            m_i[i] = mnew;
            float rsum = 0.f;
#pragma unroll
            for (int j = 0; j < 4; j++) {
                float p = __expf(sc[i][j] - mnew);
                sc[i][j] = p;
                rsum += p;
            }
#pragma unroll
            for (int off = 8; off > 0; off >>= 1)
                rsum += __shfl_xor_sync(0xffffffffu, rsum, off);
            l_i[i] = l_i[i] * alpha + rsum;
#pragma unroll
            for (int j = 0; j < 4; j++) o[i][j] *= alpha;
        }

        // Stage P transposed: Ps[c][r]
#pragma unroll
        for (int j = 0; j < 4; j++) {
            float4 pv = make_float4(sc[0][j], sc[1][j], sc[2][j], sc[3][j]);
            *(float4*)(Ps + (tx * 4 + j) * LDT + ty * 4) = pv;
        }
        __syncthreads();

        // O += P V
#pragma unroll
        for (int c = 0; c < TS; c++) {
            float4 p4 = *(const float4*)(Ps + c * LDT + ty * 4);
            float4 v4 = *(const float4*)(Vs + c * LDT + tx * 4);
            float pa[4] = {p4.x, p4.y, p4.z, p4.w};
            float vb[4] = {v4.x, v4.y, v4.z, v4.w};
#pragma unroll
            for (int i = 0; i < 4; i++)
#pragma unroll
                for (int j = 0; j < 4; j++)
                    o[i][j] += pa[i] * vb[j];
        }
    }

    // Normalize and write out in [B,S,D] layout (heads concatenated)
    float* Ob = O + ((size_t)b * PS + (size_t)jq * TS) * PD + h * PDK;
#pragma unroll
    for (int i = 0; i < 4; i++) {
        float inv = 1.f / l_i[i];
        float4 r = make_float4(o[i][0] * inv, o[i][1] * inv,
                               o[i][2] * inv, o[i][3] * inv);
        *(float4*)(Ob + (size_t)(ty * 4 + i) * PD + tx * 4) = r;
    }
}

// ---------------------------------------------------------------------------
extern "C" void kernel_launch(void* const* d_in, const int* in_sizes, int n_in,
                              void* d_out, int out_size)
{
    (void)in_sizes; (void)n_in; (void)out_size;
    const float* query = (const float*)d_in[0];
    const float* key   = (const float*)d_in[1];
    const float* value = (const float*)d_in[2];
    // d_in[3] = mask: causal tril by construction; applied analytically.
    const float* Wq = (const float*)d_in[4];
    const float* bq = (const float*)d_in[5];
    const float* Wk = (const float*)d_in[6];
    const float* bk = (const float*)d_in[7];
    const float* Wv = (const float*)d_in[8];
    const float* bv = (const float*)d_in[9];
    const float* Wo = (const float*)d_in[10];
    const float* bo = (const float*)d_in[11];

    float *Qp, *Kp, *Vp, *Ap;
    cudaGetSymbolAddress((void**)&Qp, g_Q);
    cudaGetSymbolAddress((void**)&Kp, g_K);
    cudaGetSymbolAddress((void**)&Vp, g_V);
    cudaGetSymbolAddress((void**)&Ap, g_A);

    dim3 ggrid(PD / 128, PM / 128);   // (8, 32)
    gemm_abt<<<ggrid, 256>>>(query, Wq, bq, Qp);
    gemm_abt<<<ggrid, 256>>>(key,   Wk, bk, Kp);
    gemm_abt<<<ggrid, 256>>>(value, Wv, bv, Vp);

    const int smem = 4 * 64 * 68 * (int)sizeof(float);  // 69632 B
    cudaFuncSetAttribute(attn_kernel,
                         cudaFuncAttributeMaxDynamicSharedMemorySize, smem);
    attn_kernel<<<dim3(PS / 64, PB * PH), 256, smem>>>(Qp, Kp, Vp, Ap);

    gemm_abt<<<ggrid, 256>>>(Ap, Wo, bo, (float*)d_out);
}

// round 5
// speedup vs baseline: 1.5245x; 1.5245x over previous
#include <cuda_runtime.h>
#include <cuda_bf16.h>
#include <stdint.h>
#include <math.h>

// Problem constants (fixed by the reference)
constexpr int PB = 2;      // batch
constexpr int PS = 2048;   // seq len
constexpr int PD = 1024;   // model dim
constexpr int PH = 16;     // heads
constexpr int PDK = 64;    // head dim
constexpr int PM = PB * PS;       // 4096 rows for projections
constexpr int PE = PB * PS * PD;  // elements per activation tensor

// Scratch (device globals: allocation-free, graph-capturable)
__device__ float g_Q[PE];
__device__ float g_K[PE];
__device__ float g_V[PE];
__device__ float g_A[PE];

// ---------------------------------------------------------------------------
// Helpers (base-PTX only: ldmatrix sm_75+, mma.sync bf16 sm_80+)
// ---------------------------------------------------------------------------
__device__ __forceinline__ uint32_t smem_u32(const void* p) {
    uint32_t a;
    asm("{ .reg .u64 t; cvta.to.shared.u64 t, %1; cvt.u32.u64 %0, t; }"
        : "=r"(a) : "l"(p));
    return a;
}

#define LDM_X4(r, addr) \
    asm volatile("ldmatrix.sync.aligned.m8n8.x4.shared.b16 {%0,%1,%2,%3}, [%4];" \
        : "=r"((r)[0]), "=r"((r)[1]), "=r"((r)[2]), "=r"((r)[3]) : "r"(addr))

__device__ __forceinline__ void mma16816(float* d, const uint32_t* a,
                                         const uint32_t* b) {
    asm volatile(
        "mma.sync.aligned.m16n8k16.row.col.f32.bf16.bf16.f32 "
        "{%0,%1,%2,%3}, {%4,%5,%6,%7}, {%8,%9}, {%0,%1,%2,%3};"
        : "+f"(d[0]), "+f"(d[1]), "+f"(d[2]), "+f"(d[3])
        : "r"(a[0]), "r"(a[1]), "r"(a[2]), "r"(a[3]), "r"(b[0]), "r"(b[1]));
}

// Split a float4 (4 consecutive k) into packed bf16 hi pairs and lo pairs.
__device__ __forceinline__ void cvt_hilo(float4 f, uint32_t& h0, uint32_t& h1,
                                         uint32_t& l0, uint32_t& l1) {
    __nv_bfloat162 h01 = __float22bfloat162_rn(make_float2(f.x, f.y));
    __nv_bfloat162 h23 = __float22bfloat162_rn(make_float2(f.z, f.w));
    float2 r01 = make_float2(f.x - __bfloat162float(h01.x),
                             f.y - __bfloat162float(h01.y));
    float2 r23 = make_float2(f.z - __bfloat162float(h23.x),
                             f.w - __bfloat162float(h23.y));
    __nv_bfloat162 lo01 = __float22bfloat162_rn(r01);
    __nv_bfloat162 lo23 = __float22bfloat162_rn(r23);
    h0 = reinterpret_cast<uint32_t&>(h01);
    h1 = reinterpret_cast<uint32_t&>(h23);
    l0 = reinterpret_cast<uint32_t&>(lo01);
    l1 = reinterpret_cast<uint32_t&>(lo23);
}

// ---------------------------------------------------------------------------
// Split-bf16 tensor-core GEMM: C[m,n] = sum_k A[m,k]*W[n,k] + bias[n]
// D = Ahi*Whi + Ahi*Wlo + Alo*Whi  (fp32 accumulate, rel_err ~1e-5)
// CTA 128x128, BK=32, 8 warps (4x2), double-buffered smem, sw pipeline.
// ---------------------------------------------------------------------------
constexpr int G_LDS   = 80;                 // smem row stride bytes (conflict-free)
constexpr int G_TILE  = 128 * G_LDS;        // 10240 B per matrix image
constexpr int G_STAGE = 4 * G_TILE;         // Ahi,Alo,Whi,Wlo = 40960 B
constexpr int G_SMEM  = 2 * G_STAGE;        // 81920 B

__global__ void __launch_bounds__(256, 1)
gemm_mma(const float* __restrict__ A, const float* __restrict__ W,
         const float* __restrict__ bias, float* __restrict__ C)
{
    extern __shared__ char sm_raw[];
    const uint32_t sbase = smem_u32(sm_raw);

    const int t    = threadIdx.x;
    const int lane = t & 31, wid = t >> 5;
    const int wm   = wid & 3;        // warp m index (0..3) -> m0 = wm*32
    const int wn   = wid >> 2;       // warp n index (0..1) -> n0 = wn*64
    const int bx   = blockIdx.x;     // N tile
    const int by   = blockIdx.y;     // M tile

    // ---- per-thread global-load mapping (fixed across stages) ----
    const int chunk = t & 7;         // 16B unit within a 32-float k-row chunk
    const int r0    = t >> 3;        // 0..31 base row; rows r0 + 32*i
    const float* Ag = A + (size_t)(by * 128 + r0) * PD + chunk * 4;
    const float* Wg = W + (size_t)(bx * 128 + r0) * PD + chunk * 4;
    const uint32_t soff = (uint32_t)(r0 * G_LDS + chunk * 8);

    float4 ra[4], rw[4];
    float d[2][8][4];
#pragma unroll
    for (int mt = 0; mt < 2; mt++)
#pragma unroll
        for (int nt = 0; nt < 8; nt++)
#pragma unroll
            for (int q = 0; q < 4; q++) d[mt][nt][q] = 0.f;

    // fragment address precompute
    const int g = lane >> 3, ln = lane & 7;
    // A: matrices (rows g&1 ? +8:0, col g>>1 ? +16B:0)
    const uint32_t a_row = (uint32_t)(wm * 32 + ((g & 1) << 3) + ln);
    const uint32_t a_col = (uint32_t)((g >> 1) * 16);
    // B: matrices (rows g>>1 ? +8:0, col g&1 ? +16B:0)
    const uint32_t b_row = (uint32_t)(wn * 64 + ((g >> 1) << 3) + ln);
    const uint32_t b_col = (uint32_t)((g & 1) * 16);

    constexpr int NS = PD / 32;  // 32 stages

    auto LDG = [&](int s) {
        const int k0 = s * 32;
#pragma unroll
        for (int i = 0; i < 4; i++)
            ra[i] = *(const float4*)(Ag + (size_t)(32 * i) * PD + k0);
#pragma unroll
        for (int i = 0; i < 4; i++)
            rw[i] = *(const float4*)(Wg + (size_t)(32 * i) * PD + k0);
    };

    auto STS = [&](int buf) {
        const uint32_t sb = sbase + (uint32_t)buf * G_STAGE;
#pragma unroll
        for (int i = 0; i < 4; i++) {
            uint32_t h0, h1, l0, l1;
            cvt_hilo(ra[i], h0, h1, l0, l1);
            uint32_t o = sb + soff + (uint32_t)(i * 32 * G_LDS);
            asm volatile("st.shared.v2.b32 [%0], {%1,%2};"
                         :: "r"(o), "r"(h0), "r"(h1) : "memory");
            asm volatile("st.shared.v2.b32 [%0], {%1,%2};"
                         :: "r"(o + G_TILE), "r"(l0), "r"(l1) : "memory");
        }
#pragma unroll
        for (int i = 0; i < 4; i++) {
            uint32_t h0, h1, l0, l1;
            cvt_hilo(rw[i], h0, h1, l0, l1);
            uint32_t o = sb + soff + (uint32_t)(i * 32 * G_LDS) + 2u * G_TILE;
            asm volatile("st.shared.v2.b32 [%0], {%1,%2};"
                         :: "r"(o), "r"(h0), "r"(h1) : "memory");
            asm volatile("st.shared.v2.b32 [%0], {%1,%2};"
                         :: "r"(o + G_TILE), "r"(l0), "r"(l1) : "memory");
        }
    };

    auto COMPUTE = [&](int buf) {
        const uint32_t Ahi = sbase + (uint32_t)buf * G_STAGE;
        const uint32_t Alo = Ahi + G_TILE;
        const uint32_t Whi = Ahi + 2u * G_TILE;
        const uint32_t Wlo = Ahi + 3u * G_TILE;
#pragma unroll
        for (int ks = 0; ks < 2; ks++) {
            uint32_t ah[2][4], al[2][4], wh[4][4], wl[4][4];
#pragma unroll
            for (int mt = 0; mt < 2; mt++) {
                uint32_t addr = Ahi + (a_row + mt * 16) * G_LDS + ks * 32 + a_col;
                LDM_X4(ah[mt], addr);
                LDM_X4(al[mt], addr + G_TILE);
            }
#pragma unroll
            for (int np = 0; np < 4; np++) {
                uint32_t addr = Whi + (b_row + np * 16) * G_LDS + ks * 32 + b_col;
                LDM_X4(wh[np], addr);
                LDM_X4(wl[np], addr + G_TILE);
            }
#pragma unroll
            for (int mt = 0; mt < 2; mt++)
#pragma unroll
                for (int nt = 0; nt < 8; nt++) {
                    const uint32_t* bh = &wh[nt >> 1][(nt & 1) * 2];
                    const uint32_t* bl = &wl[nt >> 1][(nt & 1) * 2];
                    mma16816(d[mt][nt], ah[mt], bh);
                    mma16816(d[mt][nt], ah[mt], bl);
                    mma16816(d[mt][nt], al[mt], bh);
                }
        }
    };

    // ---- pipeline ----
    LDG(0);
    STS(0);
    __syncthreads();
    for (int s = 0; s < NS; s++) {
        if (s + 1 < NS) LDG(s + 1);
        COMPUTE(s & 1);
        if (s + 1 < NS) STS((s + 1) & 1);
        __syncthreads();
    }

    // ---- epilogue ----
    const int gq = lane & 3, gr = lane >> 2;
    float* Cb = C + (size_t)(by * 128) * PD + bx * 128;
    const float* bb = bias + bx * 128;
#pragma unroll
    for (int mt = 0; mt < 2; mt++) {
        int r_lo = wm * 32 + mt * 16 + gr;
        int r_hi = r_lo + 8;
#pragma unroll
        for (int nt = 0; nt < 8; nt++) {
            int c = wn * 64 + nt * 8 + gq * 2;
            float b0 = bb[c], b1 = bb[c + 1];
            float2 v0 = make_float2(d[mt][nt][0] + b0, d[mt][nt][1] + b1);
            float2 v1 = make_float2(d[mt][nt][2] + b0, d[mt][nt][3] + b1);
            *(float2*)(Cb + (size_t)r_lo * PD + c) = v0;
            *(float2*)(Cb + (size_t)r_hi * PD + c) = v1;
        }
    }
}

// ---------------------------------------------------------------------------
// Causal flash attention, fp32 (unchanged from R3 — known good, 671us).
// ---------------------------------------------------------------------------
__global__ void __launch_bounds__(256)
attn_kernel(const float* __restrict__ Q, const float* __restrict__ Kin,
            const float* __restrict__ Vin, float* __restrict__ O)
{
    constexpr int TS  = 64;
    constexpr int LDT = 68;
    extern __shared__ float sm[];
    float* Qs = sm;
    float* Ks = Qs + TS * LDT;
    float* Vs = Ks + TS * LDT;
    float* Ps = Vs + TS * LDT;

    const int jq = blockIdx.x;
    const int bh = blockIdx.y;
    const int b  = bh >> 4;
    const int h  = bh & 15;
    const int t  = threadIdx.x;
    const int tx = t & 15;
    const int ty = t >> 4;

    const float* Qb = Q   + ((size_t)b * PS + (size_t)jq * TS) * PD + h * PDK;
    const float* Kb = Kin + (size_t)b * PS * PD + h * PDK;
    const float* Vb = Vin + (size_t)b * PS * PD + h * PDK;

#pragma unroll
    for (int i = 0; i < 4; i++) {
        int idx = t + i * 256;
        int row = idx >> 4;
        int kq  = (idx & 15) << 2;
        float4 qv = *(const float4*)(Qb + (size_t)row * PD + kq);
        Qs[(kq + 0) * LDT + row] = qv.x; Qs[(kq + 1) * LDT + row] = qv.y;
        Qs[(kq + 2) * LDT + row] = qv.z; Qs[(kq + 3) * LDT + row] = qv.w;
    }

    float m_i[4], l_i[4], o[4][4];
#pragma unroll
    for (int i = 0; i < 4; i++) {
        m_i[i] = -1e30f;
        l_i[i] = 0.f;
#pragma unroll
        for (int j = 0; j < 4; j++) o[i][j] = 0.f;
    }

    for (int kt = 0; kt <= jq; kt++) {
        __syncthreads();
#pragma unroll
        for (int i = 0; i < 4; i++) {
            int idx = t + i * 256;
            int row = idx >> 4;
            int kq  = (idx & 15) << 2;
            const float* kp = Kb + ((size_t)kt * TS + row) * PD + kq;
            float4 kv = *(const float4*)kp;
            Ks[(kq + 0) * LDT + row] = kv.x; Ks[(kq + 1) * LDT + row] = kv.y;
            Ks[(kq + 2) * LDT + row] = kv.z; Ks[(kq + 3) * LDT + row] = kv.w;
            const float* vp = Vb + ((size_t)kt * TS + row) * PD + kq;
            float4 vv = *(const float4*)vp;
            *(float4*)(Vs + row * LDT + kq) = vv;
        }
        __syncthreads();

        float sc[4][4];
#pragma unroll
        for (int i = 0; i < 4; i++)
#pragma unroll
            for (int j = 0; j < 4; j++) sc[i][j] = 0.f;

#pragma unroll
        for (int k = 0; k < TS; k++) {
            float4 q4 = *(const float4*)(Qs + k * LDT + ty * 4);
            float4 k4 = *(const float4*)(Ks + k * LDT + tx * 4);
            float qa[4] = {q4.x, q4.y, q4.z, q4.w};
            float kb[4] = {k4.x, k4.y, k4.z, k4.w};
#pragma unroll
            for (int i = 0; i < 4; i++)
#pragma unroll
                for (int j = 0; j < 4; j++)
                    sc[i][j] += qa[i] * kb[j];
        }

        const float scale = 0.125f;
        if (kt == jq) {
#pragma unroll
            for (int i = 0; i < 4; i++)
#pragma unroll
                for (int j = 0; j < 4; j++)
                    sc[i][j] = (tx * 4 + j <= ty * 4 + i) ? sc[i][j] * scale
                                                          : -1e30f;
        } else {
#pragma unroll
            for (int i = 0; i < 4; i++)
#pragma unroll
                for (int j = 0; j < 4; j++) sc[i][j] *= scale;
        }

#pragma unroll
        for (int i = 0; i < 4; i++) {
            float rmax = fmaxf(fmaxf(sc[i][0], sc[i][1]),
                               fmaxf(sc[i][2], sc[i][3]));
#pragma unroll
            for (int off = 8; off > 0; off >>= 1)
                rmax = fmaxf(rmax, __shfl_xor_sync(0xffffffffu, rmax, off));
            float mnew  = fmaxf(m_i[i], rmax);
            float alpha = __expf(m_i[i] - mnew);
            m_i[i] = mnew;
            float rsum = 0.f;
#pragma unroll
            for (int j = 0; j < 4; j++) {
                float p = __expf(sc[i][j] - mnew);
                sc[i][j] = p;
                rsum += p;
            }
#pragma unroll
            for (int off = 8; off > 0; off >>= 1)
                rsum += __shfl_xor_sync(0xffffffffu, rsum, off);
            l_i[i] = l_i[i] * alpha + rsum;
#pragma unroll
            for (int j = 0; j < 4; j++) o[i][j] *= alpha;
        }

#pragma unroll
        for (int j = 0; j < 4; j++) {
            float4 pv = make_float4(sc[0][j], sc[1][j], sc[2][j], sc[3][j]);
            *(float4*)(Ps + (tx * 4 + j) * LDT + ty * 4) = pv;
        }
        __syncthreads();

#pragma unroll
        for (int c = 0; c < TS; c++) {
            float4 p4 = *(const float4*)(Ps + c * LDT + ty * 4);
            float4 v4 = *(const float4*)(Vs + c * LDT + tx * 4);
            float pa[4] = {p4.x, p4.y, p4.z, p4.w};
            float vb[4] = {v4.x, v4.y, v4.z, v4.w};
#pragma unroll
            for (int i = 0; i < 4; i++)
#pragma unroll
                for (int j = 0; j < 4; j++)
                    o[i][j] += pa[i] * vb[j];
        }
    }

    float* Ob = O + ((size_t)b * PS + (size_t)jq * TS) * PD + h * PDK;
#pragma unroll
    for (int i = 0; i < 4; i++) {
        float inv = 1.f / l_i[i];
        float4 r = make_float4(o[i][0] * inv, o[i][1] * inv,
                               o[i][2] * inv, o[i][3] * inv);
        *(float4*)(Ob + (size_t)(ty * 4 + i) * PD + tx * 4) = r;
    }
}

// ---------------------------------------------------------------------------
extern "C" void kernel_launch(void* const* d_in, const int* in_sizes, int n_in,
                              void* d_out, int out_size)
{
    (void)in_sizes; (void)n_in; (void)out_size;
    const float* query = (const float*)d_in[0];
    const float* key   = (const float*)d_in[1];
    const float* value = (const float*)d_in[2];
    // d_in[3] = mask: causal tril by construction; applied analytically.
    const float* Wq = (const float*)d_in[4];
    const float* bq = (const float*)d_in[5];
    const float* Wk = (const float*)d_in[6];
    const float* bk = (const float*)d_in[7];
    const float* Wv = (const float*)d_in[8];
    const float* bv = (const float*)d_in[9];
    const float* Wo = (const float*)d_in[10];
    const float* bo = (const float*)d_in[11];

    float *Qp, *Kp, *Vp, *Ap;
    cudaGetSymbolAddress((void**)&Qp, g_Q);
    cudaGetSymbolAddress((void**)&Kp, g_K);
    cudaGetSymbolAddress((void**)&Vp, g_V);
    cudaGetSymbolAddress((void**)&Ap, g_A);

    cudaFuncSetAttribute(gemm_mma,
                         cudaFuncAttributeMaxDynamicSharedMemorySize, G_SMEM);

    dim3 ggrid(PD / 128, PM / 128);   // (8, 32)
    gemm_mma<<<ggrid, 256, G_SMEM>>>(query, Wq, bq, Qp);
    gemm_mma<<<ggrid, 256, G_SMEM>>>(key,   Wk, bk, Kp);
    gemm_mma<<<ggrid, 256, G_SMEM>>>(value, Wv, bv, Vp);

    const int smem = 4 * 64 * 68 * (int)sizeof(float);  // 69632 B
    cudaFuncSetAttribute(attn_kernel,
                         cudaFuncAttributeMaxDynamicSharedMemorySize, smem);
    attn_kernel<<<dim3(PS / 64, PB * PH), 256, smem>>>(Qp, Kp, Vp, Ap);

    gemm_mma<<<ggrid, 256, G_SMEM>>>(Ap, Wo, bo, (float*)d_out);
}

// round 6
// speedup vs baseline: 2.7870x; 1.8282x over previous
#include <cuda_runtime.h>
#include <cuda_bf16.h>
#include <stdint.h>
#include <math.h>

// Problem constants (fixed by the reference)
constexpr int PB = 2;      // batch
constexpr int PS = 2048;   // seq len
constexpr int PD = 1024;   // model dim
constexpr int PH = 16;     // heads
constexpr int PDK = 64;    // head dim
constexpr int PM = PB * PS;       // 4096 rows for projections
constexpr int PE = PB * PS * PD;  // elements per activation tensor

// Scratch (device globals: allocation-free, graph-capturable)
__device__ float g_Q[PE];
__device__ float g_K[PE];
__device__ float g_V[PE];
__device__ float g_A[PE];

// ---------------------------------------------------------------------------
// Helpers (base-PTX only: ldmatrix sm_75+, mma.sync bf16 sm_80+)
// ---------------------------------------------------------------------------
__device__ __forceinline__ uint32_t smem_u32(const void* p) {
    uint32_t a;
    asm("{ .reg .u64 t; cvta.to.shared.u64 t, %1; cvt.u32.u64 %0, t; }"
        : "=r"(a) : "l"(p));
    return a;
}

#define LDM_X4(r, addr) \
    asm volatile("ldmatrix.sync.aligned.m8n8.x4.shared.b16 {%0,%1,%2,%3}, [%4];" \
        : "=r"((r)[0]), "=r"((r)[1]), "=r"((r)[2]), "=r"((r)[3]) : "r"(addr))

#define LDM_X4_T(r, addr) \
    asm volatile("ldmatrix.sync.aligned.m8n8.x4.trans.shared.b16 {%0,%1,%2,%3}, [%4];" \
        : "=r"((r)[0]), "=r"((r)[1]), "=r"((r)[2]), "=r"((r)[3]) : "r"(addr))

__device__ __forceinline__ void mma16816(float* d, const uint32_t* a,
                                         const uint32_t* b) {
    asm volatile(
        "mma.sync.aligned.m16n8k16.row.col.f32.bf16.bf16.f32 "
        "{%0,%1,%2,%3}, {%4,%5,%6,%7}, {%8,%9}, {%0,%1,%2,%3};"
        : "+f"(d[0]), "+f"(d[1]), "+f"(d[2]), "+f"(d[3])
        : "r"(a[0]), "r"(a[1]), "r"(a[2]), "r"(a[3]), "r"(b[0]), "r"(b[1]));
}

// Split a float4 (4 consecutive k) into packed bf16 hi pairs and lo pairs.
__device__ __forceinline__ void cvt_hilo(float4 f, uint32_t& h0, uint32_t& h1,
                                         uint32_t& l0, uint32_t& l1) {
    __nv_bfloat162 h01 = __float22bfloat162_rn(make_float2(f.x, f.y));
    __nv_bfloat162 h23 = __float22bfloat162_rn(make_float2(f.z, f.w));
    float2 r01 = make_float2(f.x - __bfloat162float(h01.x),
                             f.y - __bfloat162float(h01.y));
    float2 r23 = make_float2(f.z - __bfloat162float(h23.x),
                             f.w - __bfloat162float(h23.y));
    __nv_bfloat162 lo01 = __float22bfloat162_rn(r01);
    __nv_bfloat162 lo23 = __float22bfloat162_rn(r23);
    h0 = reinterpret_cast<uint32_t&>(h01);
    h1 = reinterpret_cast<uint32_t&>(h23);
    l0 = reinterpret_cast<uint32_t&>(lo01);
    l1 = reinterpret_cast<uint32_t&>(lo23);
}

// ---------------------------------------------------------------------------
// Split-bf16 tensor-core GEMM: C[m,n] = sum_k A[m,k]*W[n,k] + bias[n]
// (unchanged from R5 — measured ~75us per GEMM)
// ---------------------------------------------------------------------------
constexpr int G_LDS   = 80;
constexpr int G_TILE  = 128 * G_LDS;
constexpr int G_STAGE = 4 * G_TILE;
constexpr int G_SMEM  = 2 * G_STAGE;

__global__ void __launch_bounds__(256, 1)
gemm_mma(const float* __restrict__ A, const float* __restrict__ W,
         const float* __restrict__ bias, float* __restrict__ C)
{
    extern __shared__ char sm_raw[];
    const uint32_t sbase = smem_u32(sm_raw);

    const int t    = threadIdx.x;
    const int lane = t & 31, wid = t >> 5;
    const int wm   = wid & 3;
    const int wn   = wid >> 2;
    const int bx   = blockIdx.x;
    const int by   = blockIdx.y;

    const int chunk = t & 7;
    const int r0    = t >> 3;
    const float* Ag = A + (size_t)(by * 128 + r0) * PD + chunk * 4;
    const float* Wg = W + (size_t)(bx * 128 + r0) * PD + chunk * 4;
    const uint32_t soff = (uint32_t)(r0 * G_LDS + chunk * 8);

    float4 ra[4], rw[4];
    float d[2][8][4];
#pragma unroll
    for (int mt = 0; mt < 2; mt++)
#pragma unroll
        for (int nt = 0; nt < 8; nt++)
#pragma unroll
            for (int q = 0; q < 4; q++) d[mt][nt][q] = 0.f;

    const int g = lane >> 3, ln = lane & 7;
    const uint32_t a_row = (uint32_t)(wm * 32 + ((g & 1) << 3) + ln);
    const uint32_t a_col = (uint32_t)((g >> 1) * 16);
    const uint32_t b_row = (uint32_t)(wn * 64 + ((g >> 1) << 3) + ln);
    const uint32_t b_col = (uint32_t)((g & 1) * 16);

    constexpr int NS = PD / 32;

    auto LDG = [&](int s) {
        const int k0 = s * 32;
#pragma unroll
        for (int i = 0; i < 4; i++)
            ra[i] = *(const float4*)(Ag + (size_t)(32 * i) * PD + k0);
#pragma unroll
        for (int i = 0; i < 4; i++)
            rw[i] = *(const float4*)(Wg + (size_t)(32 * i) * PD + k0);
    };

    auto STS = [&](int buf) {
        const uint32_t sb = sbase + (uint32_t)buf * G_STAGE;
#pragma unroll
        for (int i = 0; i < 4; i++) {
            uint32_t h0, h1, l0, l1;
            cvt_hilo(ra[i], h0, h1, l0, l1);
            uint32_t o = sb + soff + (uint32_t)(i * 32 * G_LDS);
            asm volatile("st.shared.v2.b32 [%0], {%1,%2};"
                         :: "r"(o), "r"(h0), "r"(h1) : "memory");
            asm volatile("st.shared.v2.b32 [%0], {%1,%2};"
                         :: "r"(o + G_TILE), "r"(l0), "r"(l1) : "memory");
        }
#pragma unroll
        for (int i = 0; i < 4; i++) {
            uint32_t h0, h1, l0, l1;
            cvt_hilo(rw[i], h0, h1, l0, l1);
            uint32_t o = sb + soff + (uint32_t)(i * 32 * G_LDS) + 2u * G_TILE;
            asm volatile("st.shared.v2.b32 [%0], {%1,%2};"
                         :: "r"(o), "r"(h0), "r"(h1) : "memory");
            asm volatile("st.shared.v2.b32 [%0], {%1,%2};"
                         :: "r"(o + G_TILE), "r"(l0), "r"(l1) : "memory");
        }
    };

    auto COMPUTE = [&](int buf) {
        const uint32_t Ahi = sbase + (uint32_t)buf * G_STAGE;
        const uint32_t Whi = Ahi + 2u * G_TILE;
#pragma unroll
        for (int ks = 0; ks < 2; ks++) {
            uint32_t ah[2][4], al[2][4], wh[4][4], wl[4][4];
#pragma unroll
            for (int mt = 0; mt < 2; mt++) {
                uint32_t addr = Ahi + (a_row + mt * 16) * G_LDS + ks * 32 + a_col;
                LDM_X4(ah[mt], addr);
                LDM_X4(al[mt], addr + G_TILE);
            }
#pragma unroll
            for (int np = 0; np < 4; np++) {
                uint32_t addr = Whi + (b_row + np * 16) * G_LDS + ks * 32 + b_col;
                LDM_X4(wh[np], addr);
                LDM_X4(wl[np], addr + G_TILE);
            }
#pragma unroll
            for (int mt = 0; mt < 2; mt++)
#pragma unroll
                for (int nt = 0; nt < 8; nt++) {
                    const uint32_t* bh = &wh[nt >> 1][(nt & 1) * 2];
                    const uint32_t* bl = &wl[nt >> 1][(nt & 1) * 2];
                    mma16816(d[mt][nt], ah[mt], bh);
                    mma16816(d[mt][nt], ah[mt], bl);
                    mma16816(d[mt][nt], al[mt], bh);
                }
        }
    };

    LDG(0);
    STS(0);
    __syncthreads();
    for (int s = 0; s < NS; s++) {
        if (s + 1 < NS) LDG(s + 1);
        COMPUTE(s & 1);
        if (s + 1 < NS) STS((s + 1) & 1);
        __syncthreads();
    }

    const int gq = lane & 3, gr = lane >> 2;
    float* Cb = C + (size_t)(by * 128) * PD + bx * 128;
    const float* bb = bias + bx * 128;
#pragma unroll
    for (int mt = 0; mt < 2; mt++) {
        int r_lo = wm * 32 + mt * 16 + gr;
        int r_hi = r_lo + 8;
#pragma unroll
        for (int nt = 0; nt < 8; nt++) {
            int c = wn * 64 + nt * 8 + gq * 2;
            float b0 = bb[c], b1 = bb[c + 1];
            float2 v0 = make_float2(d[mt][nt][0] + b0, d[mt][nt][1] + b1);
            float2 v1 = make_float2(d[mt][nt][2] + b0, d[mt][nt][3] + b1);
            *(float2*)(Cb + (size_t)r_lo * PD + c) = v0;
            *(float2*)(Cb + (size_t)r_hi * PD + c) = v1;
        }
    }
}

// ---------------------------------------------------------------------------
// Tensor-core causal flash attention (split-bf16, FA2 structure).
// CTA: 128 q-rows x one (b,h). 8 warps; warp w owns q-rows [w*16, w*16+16).
// K-tile = 64 keys. Q/K/V staged as bf16 hi+lo, 144B row stride.
// S = QK^T and O += PV each computed with 3-term split MMAs.
// ---------------------------------------------------------------------------
constexpr int A_LD   = 72;               // bf16 elems per smem row (144 B)
constexpr int A_QT   = 128 * A_LD * 2;   // one Q image (bytes) = 18432
constexpr int A_KT   = 64 * A_LD * 2;    // one K/V image (bytes) = 9216
constexpr int AT_SMEM = 2 * A_QT + 4 * A_KT;  // 73728 B

__global__ void __launch_bounds__(256, 2)
attn_mma(const float* __restrict__ Q, const float* __restrict__ Kin,
         const float* __restrict__ Vin, float* __restrict__ O)
{
    extern __shared__ char sm_raw[];
    const uint32_t S0  = smem_u32(sm_raw);
    const uint32_t QHI = S0;
    const uint32_t QLO = S0 + A_QT;
    const uint32_t KHI = QLO + A_QT;
    const uint32_t KLO = KHI + A_KT;
    const uint32_t VHI = KLO + A_KT;
    const uint32_t VLO = VHI + A_KT;

    const int t = threadIdx.x, lane = t & 31, w = t >> 5;
    const int jq = 15 - (int)blockIdx.x;          // heavy tiles first
    const int bh = blockIdx.y;
    const int b  = bh >> 4, h = bh & 15;
    const int q0 = jq * 128;

    const float* Qg = Q   + ((size_t)b * PS + q0) * PD + h * PDK;
    const float* Kg = Kin + (size_t)b * PS * PD + h * PDK;
    const float* Vg = Vin + (size_t)b * PS * PD + h * PDK;

    // Stage Q (128 x 64) as hi/lo bf16
#pragma unroll
    for (int i = 0; i < 8; i++) {
        int idx = i * 256 + t;
        int row = idx >> 4, c4 = idx & 15;
        float4 f = *(const float4*)(Qg + (size_t)row * PD + c4 * 4);
        uint32_t h0, h1, l0, l1;
        cvt_hilo(f, h0, h1, l0, l1);
        uint32_t o = (uint32_t)(row * A_LD + c4 * 4) * 2;
        asm volatile("st.shared.v2.b32 [%0], {%1,%2};"
                     :: "r"(QHI + o), "r"(h0), "r"(h1) : "memory");
        asm volatile("st.shared.v2.b32 [%0], {%1,%2};"
                     :: "r"(QLO + o), "r"(l0), "r"(l1) : "memory");
    }

    float s[8][4], o_acc[8][4];
    float m0 = -1e30f, m1 = -1e30f, l0r = 0.f, l1r = 0.f;
#pragma unroll
    for (int nt = 0; nt < 8; nt++)
#pragma unroll
        for (int q = 0; q < 4; q++) o_acc[nt][q] = 0.f;

    // ldmatrix per-lane address components
    const int a_row = (lane & 7) + ((lane >> 3) & 1) * 8;   // Q row within 16
    const int a_cg  = (lane >> 4) * 8;                      // Q k-offset
    const int k_key = (lane & 7) + ((lane >> 4) & 1) * 8;   // K key within 16
    const int k_dk  = ((lane >> 3) & 1) * 8;                // K dk-offset
    const int v_key = (lane & 7) + ((lane >> 3) & 1) * 8;   // V key within 16
    const int v_dk  = (lane >> 4) * 8;                      // V dk-offset

    const int gr  = lane >> 2;          // row within 8
    const int gq2 = (lane & 3) * 2;     // col pair
    const int r0g = q0 + w * 16 + gr;
    const int r1g = r0g + 8;

    const int nkt = 2 * jq + 2;
    for (int kt = 0; kt < nkt; kt++) {
        __syncthreads();
        // Stage K and V tiles (64 x 64 each) as hi/lo bf16
#pragma unroll
        for (int i = 0; i < 4; i++) {
            int idx = i * 256 + t;
            int row = idx >> 4, c4 = idx & 15;
            uint32_t off = (uint32_t)(row * A_LD + c4 * 4) * 2;
            float4 fk = *(const float4*)(Kg + ((size_t)kt * 64 + row) * PD + c4 * 4);
            uint32_t h0, h1, l0, l1;
            cvt_hilo(fk, h0, h1, l0, l1);
            asm volatile("st.shared.v2.b32 [%0], {%1,%2};"
                         :: "r"(KHI + off), "r"(h0), "r"(h1) : "memory");
            asm volatile("st.shared.v2.b32 [%0], {%1,%2};"
                         :: "r"(KLO + off), "r"(l0), "r"(l1) : "memory");
            float4 fv = *(const float4*)(Vg + ((size_t)kt * 64 + row) * PD + c4 * 4);
            cvt_hilo(fv, h0, h1, l0, l1);
            asm volatile("st.shared.v2.b32 [%0], {%1,%2};"
                         :: "r"(VHI + off), "r"(h0), "r"(h1) : "memory");
            asm volatile("st.shared.v2.b32 [%0], {%1,%2};"
                         :: "r"(VLO + off), "r"(l0), "r"(l1) : "memory");
        }
        __syncthreads();

        // ---- S = Q K^T (split 3-term) ----
#pragma unroll
        for (int nt = 0; nt < 8; nt++)
#pragma unroll
            for (int q = 0; q < 4; q++) s[nt][q] = 0.f;

#pragma unroll
        for (int ks = 0; ks < 4; ks++) {
            uint32_t ah[4], al[4];
            uint32_t qaddr = QHI + (uint32_t)((w * 16 + a_row) * A_LD + ks * 16 + a_cg) * 2;
            LDM_X4(ah, qaddr);
            LDM_X4(al, qaddr + A_QT);
#pragma unroll
            for (int g = 0; g < 4; g++) {
                uint32_t kh[4], kl[4];
                uint32_t kaddr = KHI + (uint32_t)((g * 16 + k_key) * A_LD + ks * 16 + k_dk) * 2;
                LDM_X4(kh, kaddr);
                LDM_X4(kl, kaddr + A_KT);
                mma16816(s[2 * g],     ah, &kh[0]);
                mma16816(s[2 * g],     ah, &kl[0]);
                mma16816(s[2 * g],     al, &kh[0]);
                mma16816(s[2 * g + 1], ah, &kh[2]);
                mma16816(s[2 * g + 1], ah, &kl[2]);
                mma16816(s[2 * g + 1], al, &kh[2]);
            }
        }

        // ---- scale + causal mask + online softmax ----
        const float scale = 0.125f;
        float mn0 = m0, mn1 = m1;
        const bool diag = (kt >= 2 * jq);
#pragma unroll
        for (int nt = 0; nt < 8; nt++) {
            int colb = kt * 64 + nt * 8 + gq2;
            if (diag) {
                s[nt][0] = (colb     <= r0g) ? s[nt][0] * scale : -1e30f;
                s[nt][1] = (colb + 1 <= r0g) ? s[nt][1] * scale : -1e30f;
                s[nt][2] = (colb     <= r1g) ? s[nt][2] * scale : -1e30f;
                s[nt][3] = (colb + 1 <= r1g) ? s[nt][3] * scale : -1e30f;
            } else {
                s[nt][0] *= scale; s[nt][1] *= scale;
                s[nt][2] *= scale; s[nt][3] *= scale;
            }
            mn0 = fmaxf(mn0, fmaxf(s[nt][0], s[nt][1]));
            mn1 = fmaxf(mn1, fmaxf(s[nt][2], s[nt][3]));
        }
        mn0 = fmaxf(mn0, __shfl_xor_sync(0xffffffffu, mn0, 1));
        mn0 = fmaxf(mn0, __shfl_xor_sync(0xffffffffu, mn0, 2));
        mn1 = fmaxf(mn1, __shfl_xor_sync(0xffffffffu, mn1, 1));
        mn1 = fmaxf(mn1, __shfl_xor_sync(0xffffffffu, mn1, 2));

        float alpha0 = __expf(m0 - mn0);
        float alpha1 = __expf(m1 - mn1);
        m0 = mn0; m1 = mn1;

        float rs0 = 0.f, rs1 = 0.f;
#pragma unroll
        for (int nt = 0; nt < 8; nt++) {
            s[nt][0] = __expf(s[nt][0] - mn0);
            s[nt][1] = __expf(s[nt][1] - mn0);
            s[nt][2] = __expf(s[nt][2] - mn1);
            s[nt][3] = __expf(s[nt][3] - mn1);
            rs0 += s[nt][0] + s[nt][1];
            rs1 += s[nt][2] + s[nt][3];
        }
        rs0 += __shfl_xor_sync(0xffffffffu, rs0, 1);
        rs0 += __shfl_xor_sync(0xffffffffu, rs0, 2);
        rs1 += __shfl_xor_sync(0xffffffffu, rs1, 1);
        rs1 += __shfl_xor_sync(0xffffffffu, rs1, 2);
        l0r = l0r * alpha0 + rs0;
        l1r = l1r * alpha1 + rs1;

#pragma unroll
        for (int nt = 0; nt < 8; nt++) {
            o_acc[nt][0] *= alpha0; o_acc[nt][1] *= alpha0;
            o_acc[nt][2] *= alpha1; o_acc[nt][3] *= alpha1;
        }

        // ---- O += P V (split 3-term; P fragments straight from registers) ----
#pragma unroll
        for (int ks = 0; ks < 4; ks++) {
            uint32_t ah[4], al[4];
            cvt_hilo(make_float4(s[2 * ks][0], s[2 * ks][1],
                                 s[2 * ks][2], s[2 * ks][3]),
                     ah[0], ah[1], al[0], al[1]);
            cvt_hilo(make_float4(s[2 * ks + 1][0], s[2 * ks + 1][1],
                                 s[2 * ks + 1][2], s[2 * ks + 1][3]),
                     ah[2], ah[3], al[2], al[3]);
#pragma unroll
            for (int g = 0; g < 4; g++) {
                uint32_t vh[4], vl[4];
                uint32_t vaddr = VHI + (uint32_t)((ks * 16 + v_key) * A_LD + g * 16 + v_dk) * 2;
                LDM_X4_T(vh, vaddr);
                LDM_X4_T(vl, vaddr + A_KT);
                mma16816(o_acc[2 * g],     ah, &vh[0]);
                mma16816(o_acc[2 * g],     ah, &vl[0]);
                mma16816(o_acc[2 * g],     al, &vh[0]);
                mma16816(o_acc[2 * g + 1], ah, &vh[2]);
                mma16816(o_acc[2 * g + 1], ah, &vl[2]);
                mma16816(o_acc[2 * g + 1], al, &vh[2]);
            }
        }
    }

    // ---- normalize + write ----
    const float inv0 = 1.f / l0r;
    const float inv1 = 1.f / l1r;
    float* Ob = O + (size_t)b * PS * PD + h * PDK;
#pragma unroll
    for (int nt = 0; nt < 8; nt++) {
        int c = nt * 8 + gq2;
        float2 v0 = make_float2(o_acc[nt][0] * inv0, o_acc[nt][1] * inv0);
        float2 v1 = make_float2(o_acc[nt][2] * inv1, o_acc[nt][3] * inv1);
        *(float2*)(Ob + (size_t)r0g * PD + c) = v0;
        *(float2*)(Ob + (size_t)r1g * PD + c) = v1;
    }
}

// ---------------------------------------------------------------------------
extern "C" void kernel_launch(void* const* d_in, const int* in_sizes, int n_in,
                              void* d_out, int out_size)
{
    (void)in_sizes; (void)n_in; (void)out_size;
    const float* query = (const float*)d_in[0];
    const float* key   = (const float*)d_in[1];
    const float* value = (const float*)d_in[2];
    // d_in[3] = mask: causal tril by construction; applied analytically.
    const float* Wq = (const float*)d_in[4];
    const float* bq = (const float*)d_in[5];
    const float* Wk = (const float*)d_in[6];
    const float* bk = (const float*)d_in[7];
    const float* Wv = (const float*)d_in[8];
    const float* bv = (const float*)d_in[9];
    const float* Wo = (const float*)d_in[10];
    const float* bo = (const float*)d_in[11];

    float *Qp, *Kp, *Vp, *Ap;
    cudaGetSymbolAddress((void**)&Qp, g_Q);
    cudaGetSymbolAddress((void**)&Kp, g_K);
    cudaGetSymbolAddress((void**)&Vp, g_V);
    cudaGetSymbolAddress((void**)&Ap, g_A);

    cudaFuncSetAttribute(gemm_mma,
                         cudaFuncAttributeMaxDynamicSharedMemorySize, G_SMEM);
    cudaFuncSetAttribute(attn_mma,
                         cudaFuncAttributeMaxDynamicSharedMemorySize, AT_SMEM);

    dim3 ggrid(PD / 128, PM / 128);   // (8, 32)
    gemm_mma<<<ggrid, 256, G_SMEM>>>(query, Wq, bq, Qp);
    gemm_mma<<<ggrid, 256, G_SMEM>>>(key,   Wk, bk, Kp);
    gemm_mma<<<ggrid, 256, G_SMEM>>>(value, Wv, bv, Vp);

    attn_mma<<<dim3(PS / 128, PB * PH), 256, AT_SMEM>>>(Qp, Kp, Vp, Ap);

    gemm_mma<<<ggrid, 256, G_SMEM>>>(Ap, Wo, bo, (float*)d_out);
}

// round 7
// speedup vs baseline: 2.8179x; 1.0111x over previous
#include <cuda_runtime.h>
#include <cuda_bf16.h>
#include <stdint.h>
#include <math.h>

// Problem constants (fixed by the reference)
constexpr int PB = 2;      // batch
constexpr int PS = 2048;   // seq len
constexpr int PD = 1024;   // model dim
constexpr int PH = 16;     // heads
constexpr int PDK = 64;    // head dim
constexpr int PM = PB * PS;       // 4096 rows
constexpr int PE = PB * PS * PD;  // elements per activation tensor

// Scratch (device globals: allocation-free, graph-capturable)
__device__ __nv_bfloat16 g_Qh[PE], g_Ql[PE];
__device__ __nv_bfloat16 g_Kh[PE], g_Kl[PE];
__device__ __nv_bfloat16 g_Vh[PE], g_Vl[PE];
__device__ __nv_bfloat16 g_Ah[PE], g_Al[PE];
__device__ __nv_bfloat16 g_Wh[PD * PD], g_Wl[PD * PD];

// ---------------------------------------------------------------------------
// Helpers (base-PTX only: ldmatrix, mma.sync bf16, cp.async — all sm_80 era)
// ---------------------------------------------------------------------------
__device__ __forceinline__ uint32_t smem_u32(const void* p) {
    uint32_t a;
    asm("{ .reg .u64 t; cvta.to.shared.u64 t, %1; cvt.u32.u64 %0, t; }"
        : "=r"(a) : "l"(p));
    return a;
}

#define LDM_X4(r, addr) \
    asm volatile("ldmatrix.sync.aligned.m8n8.x4.shared.b16 {%0,%1,%2,%3}, [%4];" \
        : "=r"((r)[0]), "=r"((r)[1]), "=r"((r)[2]), "=r"((r)[3]) : "r"(addr))

#define LDM_X4_T(r, addr) \
    asm volatile("ldmatrix.sync.aligned.m8n8.x4.trans.shared.b16 {%0,%1,%2,%3}, [%4];" \
        : "=r"((r)[0]), "=r"((r)[1]), "=r"((r)[2]), "=r"((r)[3]) : "r"(addr))

#define CP16(dst, src) \
    asm volatile("cp.async.cg.shared.global [%0], [%1], 16;" \
        :: "r"(dst), "l"(src) : "memory")
#define CP_COMMIT() asm volatile("cp.async.commit_group;" ::: "memory")
#define CP_WAIT1()  asm volatile("cp.async.wait_group 1;" ::: "memory")
#define CP_WAIT0()  asm volatile("cp.async.wait_group 0;" ::: "memory")

__device__ __forceinline__ void mma16816(float* d, const uint32_t* a,
                                         const uint32_t* b) {
    asm volatile(
        "mma.sync.aligned.m16n8k16.row.col.f32.bf16.bf16.f32 "
        "{%0,%1,%2,%3}, {%4,%5,%6,%7}, {%8,%9}, {%0,%1,%2,%3};"
        : "+f"(d[0]), "+f"(d[1]), "+f"(d[2]), "+f"(d[3])
        : "r"(a[0]), "r"(a[1]), "r"(a[2]), "r"(a[3]), "r"(b[0]), "r"(b[1]));
}

__device__ __forceinline__ void cvt_hilo(float4 f, uint32_t& h0, uint32_t& h1,
                                         uint32_t& l0, uint32_t& l1) {
    __nv_bfloat162 h01 = __float22bfloat162_rn(make_float2(f.x, f.y));
    __nv_bfloat162 h23 = __float22bfloat162_rn(make_float2(f.z, f.w));
    float2 r01 = make_float2(f.x - __bfloat162float(h01.x),
                             f.y - __bfloat162float(h01.y));
    float2 r23 = make_float2(f.z - __bfloat162float(h23.x),
                             f.w - __bfloat162float(h23.y));
    __nv_bfloat162 lo01 = __float22bfloat162_rn(r01);
    __nv_bfloat162 lo23 = __float22bfloat162_rn(r23);
    h0 = reinterpret_cast<uint32_t&>(h01);
    h1 = reinterpret_cast<uint32_t&>(h23);
    l0 = reinterpret_cast<uint32_t&>(lo01);
    l1 = reinterpret_cast<uint32_t&>(lo23);
}

__device__ __forceinline__ uint32_t pack_hi2(float a, float b) {
    __nv_bfloat162 h = __float22bfloat162_rn(make_float2(a, b));
    return reinterpret_cast<uint32_t&>(h);
}
__device__ __forceinline__ uint32_t pack_lo2(float a, float b, uint32_t hi) {
    __nv_bfloat162 h = reinterpret_cast<__nv_bfloat162&>(hi);
    __nv_bfloat162 l = __float22bfloat162_rn(
        make_float2(a - __bfloat162float(h.x), b - __bfloat162float(h.y)));
    return reinterpret_cast<uint32_t&>(l);
}

// ---------------------------------------------------------------------------
// Weight pre-convert: fp32 [PD*PD] -> bf16 hi/lo
// ---------------------------------------------------------------------------
__global__ void __launch_bounds__(256)
convw(const float* __restrict__ W, __nv_bfloat16* __restrict__ Wh,
      __nv_bfloat16* __restrict__ Wl)
{
    int i = blockIdx.x * 256 + threadIdx.x;     // float4 index
    float4 f = ((const float4*)W)[i];
    uint32_t h0, h1, l0, l1;
    cvt_hilo(f, h0, h1, l0, l1);
    ((uint2*)Wh)[i] = make_uint2(h0, h1);
    ((uint2*)Wl)[i] = make_uint2(l0, l1);
}

// ---------------------------------------------------------------------------
// Split-bf16 tensor-core GEMM: C[m,n] = sum_k A[m,k]*W[n,k] + bias[n]
// W always via cp.async from pre-converted hi/lo. A either fp32 (in-kernel
// convert, QKV gemms) or hi/lo via cp.async (final gemm). Output either
// hi/lo bf16 (QKV) or fp32 (final).
// Tiles: CTA 128x128, BK=32, 8 warps (4x2). smem 64B rows, XOR seg swizzle.
// ---------------------------------------------------------------------------
constexpr int GB_IMG = 128 * 64;        // 8192 B per hi (or lo) image
constexpr int GB_ST  = 2 * GB_IMG;      // 16384 B per stage (hi+lo)
constexpr int NS_G   = PD / 32;         // 32 stages

template <bool A_ASYNC, bool OUT_HILO>
__global__ void __launch_bounds__(256, 2)
gemm_bf16(const float* __restrict__ A32,
          const __nv_bfloat16* __restrict__ Ahp,
          const __nv_bfloat16* __restrict__ Alp,
          const __nv_bfloat16* __restrict__ Whp,
          const __nv_bfloat16* __restrict__ Wlp,
          const float* __restrict__ bias,
          float* __restrict__ Cf,
          __nv_bfloat16* __restrict__ Chp,
          __nv_bfloat16* __restrict__ Clp)
{
    constexpr int NA = A_ASYNC ? 3 : 2;          // A stage count
    extern __shared__ char sm_raw[];
    const uint32_t SA = smem_u32(sm_raw);
    const uint32_t SW = SA + (uint32_t)NA * GB_ST;

    const int t = threadIdx.x, lane = t & 31, wid = t >> 5;
    const int wm = wid & 3, wn = wid >> 2;
    const int m0 = blockIdx.y * 128, n0 = blockIdx.x * 128;

    // A sync-load mapping (A_ASYNC=false)
    const int chunk = t & 7, r0 = t >> 3;
    const float* Ag = A_ASYNC ? nullptr
                              : A32 + (size_t)(m0 + r0) * PD + chunk * 4;
    float4 ra[4];

    float d[2][8][4];
#pragma unroll
    for (int mt = 0; mt < 2; mt++)
#pragma unroll
        for (int nt = 0; nt < 8; nt++)
#pragma unroll
            for (int q = 0; q < 4; q++) d[mt][nt][q] = 0.f;

    // ldmatrix lane geometry
    const int a_rl  = (lane & 7) + ((lane >> 3) & 1) * 8;  // A row within 16
    const int a_ks  = lane >> 4;                            // A k-seg extra
    const int b_rl  = (lane & 7) + ((lane >> 4) & 1) * 8;  // W row within 16
    const int b_ks  = (lane >> 3) & 1;                      // W k-seg extra

    auto LDGA = [&](int s) {
        const int k0 = s * 32;
#pragma unroll
        for (int i = 0; i < 4; i++)
            ra[i] = *(const float4*)(Ag + (size_t)(32 * i) * PD + k0);
    };
    auto STSA = [&](int s) {
        const uint32_t base = SA + (uint32_t)(s & 1) * GB_ST;
        const int seg = chunk >> 1;
#pragma unroll
        for (int i = 0; i < 4; i++) {
            int row = r0 + 32 * i;
            uint32_t h0, h1, l0, l1;
            cvt_hilo(ra[i], h0, h1, l0, l1);
            uint32_t addr = base + (uint32_t)(row * 64 +
                            ((seg ^ ((row >> 1) & 3)) * 16) + (chunk & 1) * 8);
            asm volatile("st.shared.v2.b32 [%0], {%1,%2};"
                         :: "r"(addr), "r"(h0), "r"(h1) : "memory");
            asm volatile("st.shared.v2.b32 [%0], {%1,%2};"
                         :: "r"(addr + GB_IMG), "r"(l0), "r"(l1) : "memory");
        }
    };
    auto CPA = [&](int s) {
        const uint32_t base = SA + (uint32_t)(s % 3) * GB_ST;
        const int k0 = s * 32, seg = t & 3;
#pragma unroll
        for (int i = 0; i < 2; i++) {
            int row = (t >> 2) + i * 64;
            uint32_t dst = base + (uint32_t)(row * 64 +
                           ((seg ^ ((row >> 1) & 3)) * 16));
            size_t go = (size_t)(m0 + row) * PD + k0 + seg * 8;
            CP16(dst, Ahp + go);
            CP16(dst + GB_IMG, Alp + go);
        }
    };
    auto CPW = [&](int s) {
        const uint32_t base = SW + (uint32_t)(s % 3) * GB_ST;
        const int k0 = s * 32, seg = t & 3;
#pragma unroll
        for (int i = 0; i < 2; i++) {
            int row = (t >> 2) + i * 64;
            uint32_t dst = base + (uint32_t)(row * 64 +
                           ((seg ^ ((row >> 1) & 3)) * 16));
            size_t go = (size_t)(n0 + row) * PD + k0 + seg * 8;
            CP16(dst, Whp + go);
            CP16(dst + GB_IMG, Wlp + go);
        }
    };

    auto COMPUTE = [&](int s) {
        const uint32_t Ab = SA + (uint32_t)(A_ASYNC ? (s % 3) : (s & 1)) * GB_ST;
        const uint32_t Wb = SW + (uint32_t)(s % 3) * GB_ST;
#pragma unroll
        for (int ks = 0; ks < 2; ks++) {
            uint32_t ah[2][4], al[2][4];
#pragma unroll
            for (int mt = 0; mt < 2; mt++) {
                int row = wm * 32 + mt * 16 + a_rl;
                int kseg = ks * 2 + a_ks;
                uint32_t addr = Ab + (uint32_t)(row * 64 +
                                ((kseg ^ ((row >> 1) & 3)) * 16));
                LDM_X4(ah[mt], addr);
                LDM_X4(al[mt], addr + GB_IMG);
            }
#pragma unroll
            for (int np = 0; np < 4; np++) {
                int row = wn * 64 + np * 16 + b_rl;
                int kseg = ks * 2 + b_ks;
                uint32_t addr = Wb + (uint32_t)(row * 64 +
                                ((kseg ^ ((row >> 1) & 3)) * 16));
                uint32_t wh[4], wl[4];
                LDM_X4(wh, addr);
                LDM_X4(wl, addr + GB_IMG);
#pragma unroll
                for (int mt = 0; mt < 2; mt++) {
                    mma16816(d[mt][np * 2],     ah[mt], &wh[0]);
                    mma16816(d[mt][np * 2],     ah[mt], &wl[0]);
                    mma16816(d[mt][np * 2],     al[mt], &wh[0]);
                    mma16816(d[mt][np * 2 + 1], ah[mt], &wh[2]);
                    mma16816(d[mt][np * 2 + 1], ah[mt], &wl[2]);
                    mma16816(d[mt][np * 2 + 1], al[mt], &wh[2]);
                }
            }
        }
    };

    // ---- pipeline ----
    if (!A_ASYNC) LDGA(0);
    CPW(0); if (A_ASYNC) CPA(0); CP_COMMIT();
    CPW(1); if (A_ASYNC) CPA(1); CP_COMMIT();
    if (!A_ASYNC) STSA(0);
    CP_WAIT1();
    __syncthreads();

    for (int s = 0; s < NS_G; s++) {
        if (!A_ASYNC) { if (s + 1 < NS_G) LDGA(s + 1); }
        if (s + 2 < NS_G) { CPW(s + 2); if (A_ASYNC) CPA(s + 2); CP_COMMIT(); }
        COMPUTE(s);
        if (!A_ASYNC) { if (s + 1 < NS_G) STSA(s + 1); }
        if (s + 2 < NS_G) CP_WAIT1(); else CP_WAIT0();
        __syncthreads();
    }

    // ---- epilogue ----
    const int gq = lane & 3, gr = lane >> 2;
    const float* bb = bias + n0;
#pragma unroll
    for (int mt = 0; mt < 2; mt++) {
        int r_lo = wm * 32 + mt * 16 + gr;
        int r_hi = r_lo + 8;
#pragma unroll
        for (int nt = 0; nt < 8; nt++) {
            int c = wn * 64 + nt * 8 + gq * 2;
            float b0 = bb[c], b1 = bb[c + 1];
            float v00 = d[mt][nt][0] + b0, v01 = d[mt][nt][1] + b1;
            float v10 = d[mt][nt][2] + b0, v11 = d[mt][nt][3] + b1;
            if (OUT_HILO) {
                size_t i0 = (size_t)(m0 + r_lo) * PD + n0 + c;
                size_t i1 = (size_t)(m0 + r_hi) * PD + n0 + c;
                uint32_t h0 = pack_hi2(v00, v01);
                uint32_t h1 = pack_hi2(v10, v11);
                *(uint32_t*)(Chp + i0) = h0;
                *(uint32_t*)(Chp + i1) = h1;
                *(uint32_t*)(Clp + i0) = pack_lo2(v00, v01, h0);
                *(uint32_t*)(Clp + i1) = pack_lo2(v10, v11, h1);
            } else {
                *(float2*)(Cf + (size_t)(m0 + r_lo) * PD + n0 + c) =
                    make_float2(v00, v01);
                *(float2*)(Cf + (size_t)(m0 + r_hi) * PD + n0 + c) =
                    make_float2(v10, v11);
            }
        }
    }
}

// ---------------------------------------------------------------------------
// Tensor-core causal flash attention, all-cp.async staging of hi/lo bf16.
// CTA: 128 q-rows x one (b,h). 8 warps. K-tile = 64 keys, double-buffered.
// smem: 128B rows, XOR seg swizzle (seg ^ (row & 7)).
// ---------------------------------------------------------------------------
constexpr int AQ_IMG = 128 * 128;   // 16384 B
constexpr int AK_IMG = 64 * 128;    // 8192 B
constexpr int AT_SMEM = 2 * AQ_IMG + 2 * 4 * AK_IMG;  // 98304 B

__global__ void __launch_bounds__(256, 2)
attn_mma(const __nv_bfloat16* __restrict__ Qhp, const __nv_bfloat16* __restrict__ Qlp,
         const __nv_bfloat16* __restrict__ Khp, const __nv_bfloat16* __restrict__ Klp,
         const __nv_bfloat16* __restrict__ Vhp, const __nv_bfloat16* __restrict__ Vlp,
         __nv_bfloat16* __restrict__ Ahp, __nv_bfloat16* __restrict__ Alp)
{
    extern __shared__ char sm_raw[];
    const uint32_t S0  = smem_u32(sm_raw);
    const uint32_t QHI = S0, QLO = S0 + AQ_IMG;
    const uint32_t KVB = S0 + 2 * AQ_IMG;       // + buf*32768

    const int t = threadIdx.x, lane = t & 31, w = t >> 5;
    const int jq = 15 - (int)blockIdx.x;        // heavy tiles first
    const int bh = blockIdx.y;
    const int b  = bh >> 4, h = bh & 15;
    const int q0 = jq * 128;

    const size_t gQ = ((size_t)b * PS + q0) * PD + h * PDK;
    const size_t gKV = (size_t)b * PS * PD + h * PDK;

    // ---- prologue: Q + KV0 (group 0), KV1 (group 1) ----
#pragma unroll
    for (int i = 0; i < 8; i++) {               // Q: 2048 segs / 256 thr
        int rem = (i & 3) * 256 + t;
        int row = rem >> 3, seg = rem & 7;
        uint32_t dst = (i < 4 ? QHI : QLO) +
                       (uint32_t)(row * 128 + ((seg ^ (row & 7)) * 16));
        const __nv_bfloat16* src = (i < 4 ? Qhp : Qlp) +
                                   gQ + (size_t)row * PD + seg * 8;
        CP16(dst, src);
    }
    auto CPKV = [&](int kt, uint32_t base) {
#pragma unroll
        for (int i = 0; i < 8; i++) {
            int img = i >> 1;                    // 0=Kh 1=Kl 2=Vh 3=Vl
            int rem = (i & 1) * 256 + t;
            int row = rem >> 3, seg = rem & 7;
            uint32_t dst = base + (uint32_t)img * AK_IMG +
                           (uint32_t)(row * 128 + ((seg ^ (row & 7)) * 16));
            const __nv_bfloat16* p = (img == 0) ? Khp : (img == 1) ? Klp
                                   : (img == 2) ? Vhp : Vlp;
            CP16(dst, p + gKV + (size_t)(kt * 64 + row) * PD + seg * 8);
        }
    };
    CPKV(0, KVB); CP_COMMIT();
    CPKV(1, KVB + 32768u); CP_COMMIT();

    float s[8][4], o_acc[8][4];
    float m0r = -1e30f, m1r = -1e30f, l0r = 0.f, l1r = 0.f;
#pragma unroll
    for (int nt = 0; nt < 8; nt++)
#pragma unroll
        for (int q = 0; q < 4; q++) o_acc[nt][q] = 0.f;

    // lane geometry
    const int a_rl  = (lane & 7) + ((lane >> 3) & 1) * 8;  // Q row within 16
    const int a_ks  = lane >> 4;
    const int k_rl  = (lane & 7) + ((lane >> 4) & 1) * 8;  // K key within 16
    const int k_ks  = (lane >> 3) & 1;
    const int v_rl  = (lane & 7) + ((lane >> 3) & 1) * 8;  // V key within 16
    const int v_cs  = lane >> 4;                            // V dk seg extra

    const int gr  = lane >> 2;
    const int gq2 = (lane & 3) * 2;
    const int r0g = q0 + w * 16 + gr;
    const int r1g = r0g + 8;

    const int nkt = 2 * jq + 2;
    for (int kt = 0; kt < nkt; kt++) {
        if (kt == nkt - 1) { CP_WAIT0(); } else { CP_WAIT1(); }
        __syncthreads();
        const uint32_t KB = KVB + (uint32_t)(kt & 1) * 32768u;
        const uint32_t VB = KB + 2 * AK_IMG;

        // ---- S = Q K^T (3-term split) ----
#pragma unroll
        for (int nt = 0; nt < 8; nt++)
#pragma unroll
            for (int q = 0; q < 4; q++) s[nt][q] = 0.f;

#pragma unroll
        for (int ks = 0; ks < 4; ks++) {
            uint32_t ah[4], al[4];
            {
                int row = w * 16 + a_rl;
                int kseg = ks * 2 + a_ks;
                uint32_t qaddr = QHI + (uint32_t)(row * 128 +
                                 ((kseg ^ (row & 7)) * 16));
                LDM_X4(ah, qaddr);
                LDM_X4(al, qaddr + AQ_IMG);
            }
#pragma unroll
            for (int g = 0; g < 4; g++) {
                int row = g * 16 + k_rl;
                int kseg = ks * 2 + k_ks;
                uint32_t kaddr = KB + (uint32_t)(row * 128 +
                                 ((kseg ^ (row & 7)) * 16));
                uint32_t kh[4], kl[4];
                LDM_X4(kh, kaddr);
                LDM_X4(kl, kaddr + AK_IMG);
                mma16816(s[2 * g],     ah, &kh[0]);
                mma16816(s[2 * g],     ah, &kl[0]);
                mma16816(s[2 * g],     al, &kh[0]);
                mma16816(s[2 * g + 1], ah, &kh[2]);
                mma16816(s[2 * g + 1], ah, &kl[2]);
                mma16816(s[2 * g + 1], al, &kh[2]);
            }
        }

        // ---- scale + causal mask + online softmax ----
        const float scale = 0.125f;
        float mn0 = m0r, mn1 = m1r;
        const bool diag = (kt >= 2 * jq);
#pragma unroll
        for (int nt = 0; nt < 8; nt++) {
            int colb = kt * 64 + nt * 8 + gq2;
            if (diag) {
                s[nt][0] = (colb     <= r0g) ? s[nt][0] * scale : -1e30f;
                s[nt][1] = (colb + 1 <= r0g) ? s[nt][1] * scale : -1e30f;
                s[nt][2] = (colb     <= r1g) ? s[nt][2] * scale : -1e30f;
                s[nt][3] = (colb + 1 <= r1g) ? s[nt][3] * scale : -1e30f;
            } else {
                s[nt][0] *= scale; s[nt][1] *= scale;
                s[nt][2] *= scale; s[nt][3] *= scale;
            }
            mn0 = fmaxf(mn0, fmaxf(s[nt][0], s[nt][1]));
            mn1 = fmaxf(mn1, fmaxf(s[nt][2], s[nt][3]));
        }
        mn0 = fmaxf(mn0, __shfl_xor_sync(0xffffffffu, mn0, 1));
        mn0 = fmaxf(mn0, __shfl_xor_sync(0xffffffffu, mn0, 2));
        mn1 = fmaxf(mn1, __shfl_xor_sync(0xffffffffu, mn1, 1));
        mn1 = fmaxf(mn1, __shfl_xor_sync(0xffffffffu, mn1, 2));

        float alpha0 = __expf(m0r - mn0);
        float alpha1 = __expf(m1r - mn1);
        m0r = mn0; m1r = mn1;

        float rs0 = 0.f, rs1 = 0.f;
#pragma unroll
        for (int nt = 0; nt < 8; nt++) {
            s[nt][0] = __expf(s[nt][0] - mn0);
            s[nt][1] = __expf(s[nt][1] - mn0);
            s[nt][2] = __expf(s[nt][2] - mn1);
            s[nt][3] = __expf(s[nt][3] - mn1);
            rs0 += s[nt][0] + s[nt][1];
            rs1 += s[nt][2] + s[nt][3];
        }
        rs0 += __shfl_xor_sync(0xffffffffu, rs0, 1);
        rs0 += __shfl_xor_sync(0xffffffffu, rs0, 2);
        rs1 += __shfl_xor_sync(0xffffffffu, rs1, 1);
        rs1 += __shfl_xor_sync(0xffffffffu, rs1, 2);
        l0r = l0r * alpha0 + rs0;
        l1r = l1r * alpha1 + rs1;

#pragma unroll
        for (int nt = 0; nt < 8; nt++) {
            o_acc[nt][0] *= alpha0; o_acc[nt][1] *= alpha0;
            o_acc[nt][2] *= alpha1; o_acc[nt][3] *= alpha1;
        }

        // ---- O += P V (3-term split, P from registers) ----
#pragma unroll
        for (int ks = 0; ks < 4; ks++) {
            uint32_t ah[4], al[4];
            cvt_hilo(make_float4(s[2 * ks][0], s[2 * ks][1],
                                 s[2 * ks][2], s[2 * ks][3]),
                     ah[0], ah[1], al[0], al[1]);
            cvt_hilo(make_float4(s[2 * ks + 1][0], s[2 * ks + 1][1],
                                 s[2 * ks + 1][2], s[2 * ks + 1][3]),
                     ah[2], ah[3], al[2], al[3]);
#pragma unroll
            for (int g = 0; g < 4; g++) {
                int row = ks * 16 + v_rl;
                int cseg = g * 2 + v_cs;
                uint32_t vaddr = VB + (uint32_t)(row * 128 +
                                 ((cseg ^ (row & 7)) * 16));
                uint32_t vh[4], vl[4];
                LDM_X4_T(vh, vaddr);
                LDM_X4_T(vl, vaddr + AK_IMG);
                mma16816(o_acc[2 * g],     ah, &vh[0]);
                mma16816(o_acc[2 * g],     ah, &vl[0]);
                mma16816(o_acc[2 * g],     al, &vh[0]);
                mma16816(o_acc[2 * g + 1], ah, &vh[2]);
                mma16816(o_acc[2 * g + 1], ah, &vl[2]);
                mma16816(o_acc[2 * g + 1], al, &vh[2]);
            }
        }

        __syncthreads();
        if (kt + 2 < nkt) {
            CPKV(kt + 2, KVB + (uint32_t)(kt & 1) * 32768u);
            CP_COMMIT();
        }
    }

    // ---- normalize + write hi/lo bf16 ----
    const float inv0 = 1.f / l0r;
    const float inv1 = 1.f / l1r;
    const size_t gO = (size_t)b * PS * PD + h * PDK;
#pragma unroll
    for (int nt = 0; nt < 8; nt++) {
        int c = nt * 8 + gq2;
        float v00 = o_acc[nt][0] * inv0, v01 = o_acc[nt][1] * inv0;
        float v10 = o_acc[nt][2] * inv1, v11 = o_acc[nt][3] * inv1;
        size_t i0 = gO + (size_t)r0g * PD + c;
        size_t i1 = gO + (size_t)r1g * PD + c;
        uint32_t h0 = pack_hi2(v00, v01);
        uint32_t h1 = pack_hi2(v10, v11);
        *(uint32_t*)(Ahp + i0) = h0;
        *(uint32_t*)(Ahp + i1) = h1;
        *(uint32_t*)(Alp + i0) = pack_lo2(v00, v01, h0);
        *(uint32_t*)(Alp + i1) = pack_lo2(v10, v11, h1);
    }
}

// ---------------------------------------------------------------------------
extern "C" void kernel_launch(void* const* d_in, const int* in_sizes, int n_in,
                              void* d_out, int out_size)
{
    (void)in_sizes; (void)n_in; (void)out_size;
    const float* query = (const float*)d_in[0];
    const float* key   = (const float*)d_in[1];
    const float* value = (const float*)d_in[2];
    // d_in[3] = mask: causal tril by construction; applied analytically.
    const float* Wq = (const float*)d_in[4];
    const float* bq = (const float*)d_in[5];
    const float* Wk = (const float*)d_in[6];
    const float* bk = (const float*)d_in[7];
    const float* Wv = (const float*)d_in[8];
    const float* bv = (const float*)d_in[9];
    const float* Wo = (const float*)d_in[10];
    const float* bo = (const float*)d_in[11];

    __nv_bfloat16 *Qh, *Ql, *Kh, *Kl, *Vh, *Vl, *Ah, *Al, *Wh, *Wl;
    cudaGetSymbolAddress((void**)&Qh, g_Qh); cudaGetSymbolAddress((void**)&Ql, g_Ql);
    cudaGetSymbolAddress((void**)&Kh, g_Kh); cudaGetSymbolAddress((void**)&Kl, g_Kl);
    cudaGetSymbolAddress((void**)&Vh, g_Vh); cudaGetSymbolAddress((void**)&Vl, g_Vl);
    cudaGetSymbolAddress((void**)&Ah, g_Ah); cudaGetSymbolAddress((void**)&Al, g_Al);
    cudaGetSymbolAddress((void**)&Wh, g_Wh); cudaGetSymbolAddress((void**)&Wl, g_Wl);

    const int smA = 2 * GB_ST + 3 * GB_ST;   // 81920
    const int smB = 3 * GB_ST + 3 * GB_ST;   // 98304
    cudaFuncSetAttribute(gemm_bf16<false, true>,
                         cudaFuncAttributeMaxDynamicSharedMemorySize, smA);
    cudaFuncSetAttribute(gemm_bf16<true, false>,
                         cudaFuncAttributeMaxDynamicSharedMemorySize, smB);
    cudaFuncSetAttribute(attn_mma,
                         cudaFuncAttributeMaxDynamicSharedMemorySize, AT_SMEM);

    dim3 ggrid(PD / 128, PM / 128);   // (8, 32)
    const int cwg = (PD * PD / 4) / 256;   // 1024 blocks

    convw<<<cwg, 256>>>(Wq, Wh, Wl);
    gemm_bf16<false, true><<<ggrid, 256, smA>>>(query, nullptr, nullptr,
                                                Wh, Wl, bq, nullptr, Qh, Ql);
    convw<<<cwg, 256>>>(Wk, Wh, Wl);
    gemm_bf16<false, true><<<ggrid, 256, smA>>>(key, nullptr, nullptr,
                                                Wh, Wl, bk, nullptr, Kh, Kl);
    convw<<<cwg, 256>>>(Wv, Wh, Wl);
    gemm_bf16<false, true><<<ggrid, 256, smA>>>(value, nullptr, nullptr,
                                                Wh, Wl, bv, nullptr, Vh, Vl);

    attn_mma<<<dim3(PS / 128, PB * PH), 256, AT_SMEM>>>(Qh, Ql, Kh, Kl,
                                                        Vh, Vl, Ah, Al);

    convw<<<cwg, 256>>>(Wo, Wh, Wl);
    gemm_bf16<true, false><<<ggrid, 256, smB>>>(nullptr, Ah, Al,
                                                Wh, Wl, bo, (float*)d_out,
                                                nullptr, nullptr);
}

// round 8
// speedup vs baseline: 3.1548x; 1.1196x over previous
#include <cuda_runtime.h>
#include <cuda_bf16.h>
#include <stdint.h>
#include <math.h>

// Problem constants (fixed by the reference)
constexpr int PB = 2;      // batch
constexpr int PS = 2048;   // seq len
constexpr int PD = 1024;   // model dim
constexpr int PH = 16;     // heads
constexpr int PDK = 64;    // head dim
constexpr int PM = PB * PS;       // 4096 rows
constexpr int PE = PB * PS * PD;  // elements per activation tensor
constexpr int PW = PD * PD;       // elements per weight

// Scratch (device globals: allocation-free, graph-capturable)
// converted inputs
__device__ __nv_bfloat16 g_Xqh[PE], g_Xql[PE];   // query input hi/lo
__device__ __nv_bfloat16 g_Xkh[PE], g_Xkl[PE];   // key input
__device__ __nv_bfloat16 g_Xvh[PE], g_Xvl[PE];   // value input
__device__ __nv_bfloat16 g_Wqh[PW], g_Wql[PW];
__device__ __nv_bfloat16 g_Wkh[PW], g_Wkl[PW];
__device__ __nv_bfloat16 g_Wvh[PW], g_Wvl[PW];
__device__ __nv_bfloat16 g_Woh[PW], g_Wol[PW];
// projected activations + attn output
__device__ __nv_bfloat16 g_Qh[PE], g_Ql[PE];
__device__ __nv_bfloat16 g_Kh[PE], g_Kl[PE];
__device__ __nv_bfloat16 g_Vh[PE], g_Vl[PE];
__device__ __nv_bfloat16 g_Ah[PE], g_Al[PE];

// ---------------------------------------------------------------------------
// Helpers (base-PTX only: ldmatrix, mma.sync bf16, cp.async)
// ---------------------------------------------------------------------------
__device__ __forceinline__ uint32_t smem_u32(const void* p) {
    uint32_t a;
    asm("{ .reg .u64 t; cvta.to.shared.u64 t, %1; cvt.u32.u64 %0, t; }"
        : "=r"(a) : "l"(p));
    return a;
}

#define LDM_X4(r, addr) \
    asm volatile("ldmatrix.sync.aligned.m8n8.x4.shared.b16 {%0,%1,%2,%3}, [%4];" \
        : "=r"((r)[0]), "=r"((r)[1]), "=r"((r)[2]), "=r"((r)[3]) : "r"(addr))

#define LDM_X4_T(r, addr) \
    asm volatile("ldmatrix.sync.aligned.m8n8.x4.trans.shared.b16 {%0,%1,%2,%3}, [%4];" \
        : "=r"((r)[0]), "=r"((r)[1]), "=r"((r)[2]), "=r"((r)[3]) : "r"(addr))

#define CP16(dst, src) \
    asm volatile("cp.async.cg.shared.global [%0], [%1], 16;" \
        :: "r"(dst), "l"(src) : "memory")
#define CP_COMMIT() asm volatile("cp.async.commit_group;" ::: "memory")
#define CP_WAIT1()  asm volatile("cp.async.wait_group 1;" ::: "memory")
#define CP_WAIT0()  asm volatile("cp.async.wait_group 0;" ::: "memory")

__device__ __forceinline__ void mma16816(float* d, const uint32_t* a,
                                         const uint32_t* b) {
    asm volatile(
        "mma.sync.aligned.m16n8k16.row.col.f32.bf16.bf16.f32 "
        "{%0,%1,%2,%3}, {%4,%5,%6,%7}, {%8,%9}, {%0,%1,%2,%3};"
        : "+f"(d[0]), "+f"(d[1]), "+f"(d[2]), "+f"(d[3])
        : "r"(a[0]), "r"(a[1]), "r"(a[2]), "r"(a[3]), "r"(b[0]), "r"(b[1]));
}

__device__ __forceinline__ void cvt_hilo(float4 f, uint32_t& h0, uint32_t& h1,
                                         uint32_t& l0, uint32_t& l1) {
    __nv_bfloat162 h01 = __float22bfloat162_rn(make_float2(f.x, f.y));
    __nv_bfloat162 h23 = __float22bfloat162_rn(make_float2(f.z, f.w));
    float2 r01 = make_float2(f.x - __bfloat162float(h01.x),
                             f.y - __bfloat162float(h01.y));
    float2 r23 = make_float2(f.z - __bfloat162float(h23.x),
                             f.w - __bfloat162float(h23.y));
    __nv_bfloat162 lo01 = __float22bfloat162_rn(r01);
    __nv_bfloat162 lo23 = __float22bfloat162_rn(r23);
    h0 = reinterpret_cast<uint32_t&>(h01);
    h1 = reinterpret_cast<uint32_t&>(h23);
    l0 = reinterpret_cast<uint32_t&>(lo01);
    l1 = reinterpret_cast<uint32_t&>(lo23);
}

__device__ __forceinline__ uint32_t pack_hi2(float a, float b) {
    __nv_bfloat162 h = __float22bfloat162_rn(make_float2(a, b));
    return reinterpret_cast<uint32_t&>(h);
}
__device__ __forceinline__ uint32_t pack_lo2(float a, float b, uint32_t hi) {
    __nv_bfloat162 h = reinterpret_cast<__nv_bfloat162&>(hi);
    __nv_bfloat162 l = __float22bfloat162_rn(
        make_float2(a - __bfloat162float(h.x), b - __bfloat162float(h.y)));
    return reinterpret_cast<uint32_t&>(l);
}

// ---------------------------------------------------------------------------
// Fused convert: all 7 fp32 tensors -> bf16 hi/lo in one launch.
// ---------------------------------------------------------------------------
constexpr int ACT_B = (PE / 4) / 256;   // 4096 blocks per activation
constexpr int W_B   = (PW / 4) / 256;   // 1024 blocks per weight
constexpr int CONV_BLOCKS = 3 * ACT_B + 4 * W_B;

__global__ void __launch_bounds__(256)
convall(const float* __restrict__ q, const float* __restrict__ kk,
        const float* __restrict__ v,
        const float* __restrict__ wq, const float* __restrict__ wk,
        const float* __restrict__ wv, const float* __restrict__ wo)
{
    int bid = blockIdx.x;
    const float* src;
    __nv_bfloat16 *dh, *dl;
    if      (bid < ACT_B)          { src = q;  dh = g_Xqh; dl = g_Xql; }
    else if (bid < 2 * ACT_B)      { src = kk; dh = g_Xkh; dl = g_Xkl; bid -= ACT_B; }
    else if (bid < 3 * ACT_B)      { src = v;  dh = g_Xvh; dl = g_Xvl; bid -= 2 * ACT_B; }
    else if (bid < 3 * ACT_B + W_B)     { src = wq; dh = g_Wqh; dl = g_Wql; bid -= 3 * ACT_B; }
    else if (bid < 3 * ACT_B + 2 * W_B) { src = wk; dh = g_Wkh; dl = g_Wkl; bid -= 3 * ACT_B + W_B; }
    else if (bid < 3 * ACT_B + 3 * W_B) { src = wv; dh = g_Wvh; dl = g_Wvl; bid -= 3 * ACT_B + 2 * W_B; }
    else                                { src = wo; dh = g_Woh; dl = g_Wol; bid -= 3 * ACT_B + 3 * W_B; }

    int i = bid * 256 + threadIdx.x;   // float4 index
    float4 f = ((const float4*)src)[i];
    uint32_t h0, h1, l0, l1;
    cvt_hilo(f, h0, h1, l0, l1);
    ((uint2*)dh)[i] = make_uint2(h0, h1);
    ((uint2*)dl)[i] = make_uint2(l0, l1);
}

// ---------------------------------------------------------------------------
// Fully-async split-bf16 GEMM: C[m,n] = sum_k A[m,k]*W[n,k] + bias[n]
// blockIdx.z selects the problem (QKV batched in one launch).
// CTA 128x128, BK=32, 3-stage cp.async on both operands.
// ---------------------------------------------------------------------------
constexpr int GB_IMG = 128 * 64;        // 8192 B per hi (or lo) image
constexpr int GB_ST  = 2 * GB_IMG;      // per stage (hi+lo)
constexpr int NS_G   = PD / 32;         // 32 stages
constexpr int G_SMEM = 6 * GB_ST;       // 3 A-stages + 3 W-stages = 98304

struct GParams {
    const __nv_bfloat16* Ah[3];
    const __nv_bfloat16* Al[3];
    const __nv_bfloat16* Wh[3];
    const __nv_bfloat16* Wl[3];
    const float*         bias[3];
    __nv_bfloat16*       Ch[3];
    __nv_bfloat16*       Cl[3];
    float*               Cf;
};

template <bool OUT_HILO>
__global__ void __launch_bounds__(256, 2)
gemm_async(GParams p)
{
    extern __shared__ char sm_raw[];
    const uint32_t SA = smem_u32(sm_raw);
    const uint32_t SW = SA + 3u * GB_ST;

    const int z = blockIdx.z;
    const __nv_bfloat16* __restrict__ Ahp = p.Ah[z];
    const __nv_bfloat16* __restrict__ Alp = p.Al[z];
    const __nv_bfloat16* __restrict__ Whp = p.Wh[z];
    const __nv_bfloat16* __restrict__ Wlp = p.Wl[z];

    const int t = threadIdx.x, lane = t & 31, wid = t >> 5;
    const int wm = wid & 3, wn = wid >> 2;
    const int m0 = blockIdx.y * 128, n0 = blockIdx.x * 128;

    float d[2][8][4];
#pragma unroll
    for (int mt = 0; mt < 2; mt++)
#pragma unroll
        for (int nt = 0; nt < 8; nt++)
#pragma unroll
            for (int q = 0; q < 4; q++) d[mt][nt][q] = 0.f;

    const int a_rl = (lane & 7) + ((lane >> 3) & 1) * 8;
    const int a_ks = lane >> 4;
    const int b_rl = (lane & 7) + ((lane >> 4) & 1) * 8;
    const int b_ks = (lane >> 3) & 1;

    auto CPA = [&](int s) {
        const uint32_t base = SA + (uint32_t)(s % 3) * GB_ST;
        const int k0 = s * 32, seg = t & 3;
#pragma unroll
        for (int i = 0; i < 2; i++) {
            int row = (t >> 2) + i * 64;
            uint32_t dst = base + (uint32_t)(row * 64 +
                           ((seg ^ ((row >> 1) & 3)) * 16));
            size_t go = (size_t)(m0 + row) * PD + k0 + seg * 8;
            CP16(dst, Ahp + go);
            CP16(dst + GB_IMG, Alp + go);
        }
    };
    auto CPW = [&](int s) {
        const uint32_t base = SW + (uint32_t)(s % 3) * GB_ST;
        const int k0 = s * 32, seg = t & 3;
#pragma unroll
        for (int i = 0; i < 2; i++) {
            int row = (t >> 2) + i * 64;
            uint32_t dst = base + (uint32_t)(row * 64 +
                           ((seg ^ ((row >> 1) & 3)) * 16));
            size_t go = (size_t)(n0 + row) * PD + k0 + seg * 8;
            CP16(dst, Whp + go);
            CP16(dst + GB_IMG, Wlp + go);
        }
    };

    auto COMPUTE = [&](int s) {
        const uint32_t Ab = SA + (uint32_t)(s % 3) * GB_ST;
        const uint32_t Wb = SW + (uint32_t)(s % 3) * GB_ST;
#pragma unroll
        for (int ks = 0; ks < 2; ks++) {
            uint32_t ah[2][4], al[2][4];
#pragma unroll
            for (int mt = 0; mt < 2; mt++) {
                int row = wm * 32 + mt * 16 + a_rl;
                int kseg = ks * 2 + a_ks;
                uint32_t addr = Ab + (uint32_t)(row * 64 +
                                ((kseg ^ ((row >> 1) & 3)) * 16));
                LDM_X4(ah[mt], addr);
                LDM_X4(al[mt], addr + GB_IMG);
            }
#pragma unroll
            for (int np = 0; np < 4; np++) {
                int row = wn * 64 + np * 16 + b_rl;
                int kseg = ks * 2 + b_ks;
                uint32_t addr = Wb + (uint32_t)(row * 64 +
                                ((kseg ^ ((row >> 1) & 3)) * 16));
                uint32_t wh[4], wl[4];
                LDM_X4(wh, addr);
                LDM_X4(wl, addr + GB_IMG);
#pragma unroll
                for (int mt = 0; mt < 2; mt++) {
                    mma16816(d[mt][np * 2],     ah[mt], &wh[0]);
                    mma16816(d[mt][np * 2],     ah[mt], &wl[0]);
                    mma16816(d[mt][np * 2],     al[mt], &wh[0]);
                    mma16816(d[mt][np * 2 + 1], ah[mt], &wh[2]);
                    mma16816(d[mt][np * 2 + 1], ah[mt], &wl[2]);
                    mma16816(d[mt][np * 2 + 1], al[mt], &wh[2]);
                }
            }
        }
    };

    // ---- pipeline ----
    CPW(0); CPA(0); CP_COMMIT();
    CPW(1); CPA(1); CP_COMMIT();
    CP_WAIT1();
    __syncthreads();

    for (int s = 0; s < NS_G; s++) {
        if (s + 2 < NS_G) { CPW(s + 2); CPA(s + 2); CP_COMMIT(); }
        COMPUTE(s);
        if (s + 2 < NS_G) CP_WAIT1(); else CP_WAIT0();
        __syncthreads();
    }

    // ---- epilogue ----
    const int gq = lane & 3, gr = lane >> 2;
    const float* bb = p.bias[z] + n0;
#pragma unroll
    for (int mt = 0; mt < 2; mt++) {
        int r_lo = wm * 32 + mt * 16 + gr;
        int r_hi = r_lo + 8;
#pragma unroll
        for (int nt = 0; nt < 8; nt++) {
            int c = wn * 64 + nt * 8 + gq * 2;
            float b0 = bb[c], b1 = bb[c + 1];
            float v00 = d[mt][nt][0] + b0, v01 = d[mt][nt][1] + b1;
            float v10 = d[mt][nt][2] + b0, v11 = d[mt][nt][3] + b1;
            if (OUT_HILO) {
                size_t i0 = (size_t)(m0 + r_lo) * PD + n0 + c;
                size_t i1 = (size_t)(m0 + r_hi) * PD + n0 + c;
                uint32_t h0 = pack_hi2(v00, v01);
                uint32_t h1 = pack_hi2(v10, v11);
                *(uint32_t*)(p.Ch[z] + i0) = h0;
                *(uint32_t*)(p.Ch[z] + i1) = h1;
                *(uint32_t*)(p.Cl[z] + i0) = pack_lo2(v00, v01, h0);
                *(uint32_t*)(p.Cl[z] + i1) = pack_lo2(v10, v11, h1);
            } else {
                *(float2*)(p.Cf + (size_t)(m0 + r_lo) * PD + n0 + c) =
                    make_float2(v00, v01);
                *(float2*)(p.Cf + (size_t)(m0 + r_hi) * PD + n0 + c) =
                    make_float2(v10, v11);
            }
        }
    }
}

// ---------------------------------------------------------------------------
// Tensor-core causal flash attention, cp.async staging, q-tile PAIRING:
// CTA bx handles q-tiles (15-bx) then bx -> uniform cost, single wave.
// ---------------------------------------------------------------------------
constexpr int AQ_IMG = 128 * 128;   // 16384 B
constexpr int AK_IMG = 64 * 128;    // 8192 B
constexpr int AT_SMEM = 2 * AQ_IMG + 2 * 4 * AK_IMG;  // 98304 B

__global__ void __launch_bounds__(256, 2)
attn_mma(const __nv_bfloat16* __restrict__ Qhp, const __nv_bfloat16* __restrict__ Qlp,
         const __nv_bfloat16* __restrict__ Khp, const __nv_bfloat16* __restrict__ Klp,
         const __nv_bfloat16* __restrict__ Vhp, const __nv_bfloat16* __restrict__ Vlp,
         __nv_bfloat16* __restrict__ Ahp, __nv_bfloat16* __restrict__ Alp)
{
    extern __shared__ char sm_raw[];
    const uint32_t S0  = smem_u32(sm_raw);
    const uint32_t QHI = S0, QLO = S0 + AQ_IMG;
    const uint32_t KVB = S0 + 2 * AQ_IMG;

    const int t = threadIdx.x, lane = t & 31, w = t >> 5;
    const int bh = blockIdx.y;
    const int b  = bh >> 4, h = bh & 15;
    const size_t gKV = (size_t)b * PS * PD + h * PDK;

    // lane geometry (phase-invariant)
    const int a_rl = (lane & 7) + ((lane >> 3) & 1) * 8;
    const int a_ks = lane >> 4;
    const int k_rl = (lane & 7) + ((lane >> 4) & 1) * 8;
    const int k_ks = (lane >> 3) & 1;
    const int v_rl = (lane & 7) + ((lane >> 3) & 1) * 8;
    const int v_cs = lane >> 4;
    const int gr  = lane >> 2;
    const int gq2 = (lane & 3) * 2;

    auto CPKV = [&](int kt, uint32_t base) {
#pragma unroll
        for (int i = 0; i < 8; i++) {
            int img = i >> 1;
            int rem = (i & 1) * 256 + t;
            int row = rem >> 3, seg = rem & 7;
            uint32_t dst = base + (uint32_t)img * AK_IMG +
                           (uint32_t)(row * 128 + ((seg ^ (row & 7)) * 16));
            const __nv_bfloat16* pp = (img == 0) ? Khp : (img == 1) ? Klp
                                    : (img == 2) ? Vhp : Vlp;
            CP16(dst, pp + gKV + (size_t)(kt * 64 + row) * PD + seg * 8);
        }
    };

#pragma unroll 1
    for (int ph = 0; ph < 2; ph++) {
        const int jq = ph == 0 ? (15 - (int)blockIdx.x) : (int)blockIdx.x;
        const int q0 = jq * 128;
        const size_t gQ = ((size_t)b * PS + q0) * PD + h * PDK;
        const int r0g = q0 + w * 16 + gr;
        const int r1g = r0g + 8;

        // ---- prologue: Q + KV0 (group 0), KV1 (group 1) ----
#pragma unroll
        for (int i = 0; i < 8; i++) {
            int rem = (i & 3) * 256 + t;
            int row = rem >> 3, seg = rem & 7;
            uint32_t dst = (i < 4 ? QHI : QLO) +
                           (uint32_t)(row * 128 + ((seg ^ (row & 7)) * 16));
            const __nv_bfloat16* src = (i < 4 ? Qhp : Qlp) +
                                       gQ + (size_t)row * PD + seg * 8;
            CP16(dst, src);
        }
        CPKV(0, KVB); CP_COMMIT();
        CPKV(1, KVB + 32768u); CP_COMMIT();

        float s[8][4], o_acc[8][4];
        float m0r = -1e30f, m1r = -1e30f, l0r = 0.f, l1r = 0.f;
#pragma unroll
        for (int nt = 0; nt < 8; nt++)
#pragma unroll
            for (int q = 0; q < 4; q++) o_acc[nt][q] = 0.f;

        const int nkt = 2 * jq + 2;
        for (int kt = 0; kt < nkt; kt++) {
            if (kt == nkt - 1) { CP_WAIT0(); } else { CP_WAIT1(); }
            __syncthreads();
            const uint32_t KB = KVB + (uint32_t)(kt & 1) * 32768u;
            const uint32_t VB = KB + 2 * AK_IMG;

            // ---- S = Q K^T (3-term split) ----
#pragma unroll
            for (int nt = 0; nt < 8; nt++)
#pragma unroll
                for (int q = 0; q < 4; q++) s[nt][q] = 0.f;

#pragma unroll
            for (int ks = 0; ks < 4; ks++) {
                uint32_t ah[4], al[4];
                {
                    int row = w * 16 + a_rl;
                    int kseg = ks * 2 + a_ks;
                    uint32_t qaddr = QHI + (uint32_t)(row * 128 +
                                     ((kseg ^ (row & 7)) * 16));
                    LDM_X4(ah, qaddr);
                    LDM_X4(al, qaddr + AQ_IMG);
                }
#pragma unroll
                for (int g = 0; g < 4; g++) {
                    int row = g * 16 + k_rl;
                    int kseg = ks * 2 + k_ks;
                    uint32_t kaddr = KB + (uint32_t)(row * 128 +
                                     ((kseg ^ (row & 7)) * 16));
                    uint32_t kh[4], kl[4];
                    LDM_X4(kh, kaddr);
                    LDM_X4(kl, kaddr + AK_IMG);
                    mma16816(s[2 * g],     ah, &kh[0]);
                    mma16816(s[2 * g],     ah, &kl[0]);
                    mma16816(s[2 * g],     al, &kh[0]);
                    mma16816(s[2 * g + 1], ah, &kh[2]);
                    mma16816(s[2 * g + 1], ah, &kl[2]);
                    mma16816(s[2 * g + 1], al, &kh[2]);
                }
            }

            // ---- scale + causal mask + online softmax ----
            const float scale = 0.125f;
            float mn0 = m0r, mn1 = m1r;
            const bool diag = (kt >= 2 * jq);
#pragma unroll
            for (int nt = 0; nt < 8; nt++) {
                int colb = kt * 64 + nt * 8 + gq2;
                if (diag) {
                    s[nt][0] = (colb     <= r0g) ? s[nt][0] * scale : -1e30f;
                    s[nt][1] = (colb + 1 <= r0g) ? s[nt][1] * scale : -1e30f;
                    s[nt][2] = (colb     <= r1g) ? s[nt][2] * scale : -1e30f;
                    s[nt][3] = (colb + 1 <= r1g) ? s[nt][3] * scale : -1e30f;
                } else {
                    s[nt][0] *= scale; s[nt][1] *= scale;
                    s[nt][2] *= scale; s[nt][3] *= scale;
                }
                mn0 = fmaxf(mn0, fmaxf(s[nt][0], s[nt][1]));
                mn1 = fmaxf(mn1, fmaxf(s[nt][2], s[nt][3]));
            }
            mn0 = fmaxf(mn0, __shfl_xor_sync(0xffffffffu, mn0, 1));
            mn0 = fmaxf(mn0, __shfl_xor_sync(0xffffffffu, mn0, 2));
            mn1 = fmaxf(mn1, __shfl_xor_sync(0xffffffffu, mn1, 1));
            mn1 = fmaxf(mn1, __shfl_xor_sync(0xffffffffu, mn1, 2));

            float alpha0 = __expf(m0r - mn0);
            float alpha1 = __expf(m1r - mn1);
            m0r = mn0; m1r = mn1;

            float rs0 = 0.f, rs1 = 0.f;
#pragma unroll
            for (int nt = 0; nt < 8; nt++) {
                s[nt][0] = __expf(s[nt][0] - mn0);
                s[nt][1] = __expf(s[nt][1] - mn0);
                s[nt][2] = __expf(s[nt][2] - mn1);
                s[nt][3] = __expf(s[nt][3] - mn1);
                rs0 += s[nt][0] + s[nt][1];
                rs1 += s[nt][2] + s[nt][3];
            }
            rs0 += __shfl_xor_sync(0xffffffffu, rs0, 1);
            rs0 += __shfl_xor_sync(0xffffffffu, rs0, 2);
            rs1 += __shfl_xor_sync(0xffffffffu, rs1, 1);
            rs1 += __shfl_xor_sync(0xffffffffu, rs1, 2);
            l0r = l0r * alpha0 + rs0;
            l1r = l1r * alpha1 + rs1;

#pragma unroll
            for (int nt = 0; nt < 8; nt++) {
                o_acc[nt][0] *= alpha0; o_acc[nt][1] *= alpha0;
                o_acc[nt][2] *= alpha1; o_acc[nt][3] *= alpha1;
            }

            // ---- O += P V (3-term split, P from registers) ----
#pragma unroll
            for (int ks = 0; ks < 4; ks++) {
                uint32_t ah[4], al[4];
                cvt_hilo(make_float4(s[2 * ks][0], s[2 * ks][1],
                                     s[2 * ks][2], s[2 * ks][3]),
                         ah[0], ah[1], al[0], al[1]);
                cvt_hilo(make_float4(s[2 * ks + 1][0], s[2 * ks + 1][1],
                                     s[2 * ks + 1][2], s[2 * ks + 1][3]),
                         ah[2], ah[3], al[2], al[3]);
#pragma unroll
                for (int g = 0; g < 4; g++) {
                    int row = ks * 16 + v_rl;
                    int cseg = g * 2 + v_cs;
                    uint32_t vaddr = VB + (uint32_t)(row * 128 +
                                     ((cseg ^ (row & 7)) * 16));
                    uint32_t vh[4], vl[4];
                    LDM_X4_T(vh, vaddr);
                    LDM_X4_T(vl, vaddr + AK_IMG);
                    mma16816(o_acc[2 * g],     ah, &vh[0]);
                    mma16816(o_acc[2 * g],     ah, &vl[0]);
                    mma16816(o_acc[2 * g],     al, &vh[0]);
                    mma16816(o_acc[2 * g + 1], ah, &vh[2]);
                    mma16816(o_acc[2 * g + 1], ah, &vl[2]);
                    mma16816(o_acc[2 * g + 1], al, &vh[2]);
                }
            }

            __syncthreads();
            if (kt + 2 < nkt) {
                CPKV(kt + 2, KVB + (uint32_t)(kt & 1) * 32768u);
                CP_COMMIT();
            }
        }

        // ---- normalize + write hi/lo bf16 ----
        const float inv0 = 1.f / l0r;
        const float inv1 = 1.f / l1r;
        const size_t gO = (size_t)b * PS * PD + h * PDK;
#pragma unroll
        for (int nt = 0; nt < 8; nt++) {
            int c = nt * 8 + gq2;
            float v00 = o_acc[nt][0] * inv0, v01 = o_acc[nt][1] * inv0;
            float v10 = o_acc[nt][2] * inv1, v11 = o_acc[nt][3] * inv1;
            size_t i0 = gO + (size_t)r0g * PD + c;
            size_t i1 = gO + (size_t)r1g * PD + c;
            uint32_t h0 = pack_hi2(v00, v01);
            uint32_t h1 = pack_hi2(v10, v11);
            *(uint32_t*)(Ahp + i0) = h0;
            *(uint32_t*)(Ahp + i1) = h1;
            *(uint32_t*)(Alp + i0) = pack_lo2(v00, v01, h0);
            *(uint32_t*)(Alp + i1) = pack_lo2(v10, v11, h1);
        }
    }
}

// ---------------------------------------------------------------------------
extern "C" void kernel_launch(void* const* d_in, const int* in_sizes, int n_in,
                              void* d_out, int out_size)
{
    (void)in_sizes; (void)n_in; (void)out_size;
    const float* query = (const float*)d_in[0];
    const float* key   = (const float*)d_in[1];
    const float* value = (const float*)d_in[2];
    // d_in[3] = mask: causal tril by construction; applied analytically.
    const float* bq = (const float*)d_in[5];
    const float* bk = (const float*)d_in[7];
    const float* bv = (const float*)d_in[9];
    const float* bo = (const float*)d_in[11];

    auto sym = [](const void* s) {
        void* p; cudaGetSymbolAddress(&p, s); return (__nv_bfloat16*)p;
    };
    __nv_bfloat16 *Xqh = sym(g_Xqh), *Xql = sym(g_Xql);
    __nv_bfloat16 *Xkh = sym(g_Xkh), *Xkl = sym(g_Xkl);
    __nv_bfloat16 *Xvh = sym(g_Xvh), *Xvl = sym(g_Xvl);
    __nv_bfloat16 *Wqh = sym(g_Wqh), *Wql = sym(g_Wql);
    __nv_bfloat16 *Wkh = sym(g_Wkh), *Wkl = sym(g_Wkl);
    __nv_bfloat16 *Wvh = sym(g_Wvh), *Wvl = sym(g_Wvl);
    __nv_bfloat16 *Woh = sym(g_Woh), *Wol = sym(g_Wol);
    __nv_bfloat16 *Qh = sym(g_Qh), *Ql = sym(g_Ql);
    __nv_bfloat16 *Kh = sym(g_Kh), *Kl = sym(g_Kl);
    __nv_bfloat16 *Vh = sym(g_Vh), *Vl = sym(g_Vl);
    __nv_bfloat16 *Ah = sym(g_Ah), *Al = sym(g_Al);

    cudaFuncSetAttribute(gemm_async<true>,
                         cudaFuncAttributeMaxDynamicSharedMemorySize, G_SMEM);
    cudaFuncSetAttribute(gemm_async<false>,
                         cudaFuncAttributeMaxDynamicSharedMemorySize, G_SMEM);
    cudaFuncSetAttribute(attn_mma,
                         cudaFuncAttributeMaxDynamicSharedMemorySize, AT_SMEM);

    // 1. convert everything
    convall<<<CONV_BLOCKS, 256>>>(query, key, value,
                                  (const float*)d_in[4], (const float*)d_in[6],
                                  (const float*)d_in[8], (const float*)d_in[10]);

    // 2. QKV projections, batched in one launch (grid.z = 3)
    GParams pq = {};
    pq.Ah[0] = Xqh; pq.Al[0] = Xql; pq.Wh[0] = Wqh; pq.Wl[0] = Wql;
    pq.bias[0] = bq; pq.Ch[0] = Qh; pq.Cl[0] = Ql;
    pq.Ah[1] = Xkh; pq.Al[1] = Xkl; pq.Wh[1] = Wkh; pq.Wl[1] = Wkl;
    pq.bias[1] = bk; pq.Ch[1] = Kh; pq.Cl[1] = Kl;
    pq.Ah[2] = Xvh; pq.Al[2] = Xvl; pq.Wh[2] = Wvh; pq.Wl[2] = Wvl;
    pq.bias[2] = bv; pq.Ch[2] = Vh; pq.Cl[2] = Vl;
    gemm_async<true><<<dim3(PD / 128, PM / 128, 3), 256, G_SMEM>>>(pq);

    // 3. attention (paired q-tiles, single wave)
    attn_mma<<<dim3(8, PB * PH), 256, AT_SMEM>>>(Qh, Ql, Kh, Kl, Vh, Vl, Ah, Al);

    // 4. output projection
    GParams po = {};
    po.Ah[0] = Ah; po.Al[0] = Al; po.Wh[0] = Woh; po.Wl[0] = Wol;
    po.bias[0] = bo; po.Cf = (float*)d_out;
    gemm_async<false><<<dim3(PD / 128, PM / 128, 1), 256, G_SMEM>>>(po);
}